// round 14
// baseline (speedup 1.0000x reference)
#include <cuda_runtime.h>
#include <cuda_bf16.h>
#include <cstdint>
#include <math.h>

#define BB 2
#define CC 256
#define NNT 13824
#define NHH 4
#define MTOT (BB*NNT)

// ---------------- scratch ----------------
__device__ __nv_bfloat16 g_h1b[BB*CC*NNT];
__device__ __nv_bfloat16 g_c2b[BB*CC*NNT];
__device__ __nv_bfloat16 g_xt_bf [BB*NNT*CC];
__device__ __nv_bfloat16 g_xct_bf[BB*NNT*CC];
__device__ __nv_bfloat16 g_qkv_bf[(size_t)BB*NNT*768];
__device__ __nv_bfloat16 g_sa_bf [BB*NNT*CC];
__device__ __nv_bfloat16 g_wqkv_bf[256*768];
__device__ __nv_bfloat16 g_wo1_bf [256*128];
__device__ __nv_bfloat16 g_wo2_bf [256*128];
__device__ __nv_bfloat16 g_we_bf  [NNT*64];
#define ZOFF_POOL 0
#define ZOFF_QSS  512
#define ZOFF_CS1S 1024
#define ZOFF_CS1Q 1536
#define ZOFF_CS2S 2048
#define ZOFF_CS2Q 2560
#define ZOFF_KP   3072
#define ZOFF_VP   35840
#define ZTOT      68608
__device__ float g_zero[ZTOT];
__device__ float g_gate[BB*CC];

// ---------------- asm helpers ----------------
__device__ __forceinline__ void ldm_x4(unsigned int (&r)[4], const void* p) {
    unsigned int a = (unsigned int)__cvta_generic_to_shared(p);
    asm volatile("ldmatrix.sync.aligned.m8n8.x4.shared.b16 {%0,%1,%2,%3}, [%4];"
        : "=r"(r[0]),"=r"(r[1]),"=r"(r[2]),"=r"(r[3]) : "r"(a));
}
__device__ __forceinline__ void ldm_x4_t(unsigned int (&r)[4], const void* p) {
    unsigned int a = (unsigned int)__cvta_generic_to_shared(p);
    asm volatile("ldmatrix.sync.aligned.m8n8.x4.trans.shared.b16 {%0,%1,%2,%3}, [%4];"
        : "=r"(r[0]),"=r"(r[1]),"=r"(r[2]),"=r"(r[3]) : "r"(a));
}
__device__ __forceinline__ void mma16816(float (&d)[4], const unsigned int (&a)[4],
                                         unsigned int b0, unsigned int b1) {
    asm volatile("mma.sync.aligned.m16n8k16.row.col.f32.bf16.bf16.f32 "
        "{%0,%1,%2,%3},{%4,%5,%6,%7},{%8,%9},{%0,%1,%2,%3};"
        : "+f"(d[0]),"+f"(d[1]),"+f"(d[2]),"+f"(d[3])
        : "r"(a[0]),"r"(a[1]),"r"(a[2]),"r"(a[3]),"r"(b0),"r"(b1));
}
__device__ __forceinline__ void cpa16(void* dst, const void* src) {
    unsigned int d = (unsigned int)__cvta_generic_to_shared(dst);
    asm volatile("cp.async.cg.shared.global [%0], [%1], 16;" :: "r"(d), "l"(src));
}
__device__ __forceinline__ void cp_commit() { asm volatile("cp.async.commit_group;"); }
template<int N> __device__ __forceinline__ void cp_wait() {
    asm volatile("cp.async.wait_group %0;" :: "n"(N));
}

// ---------------- kernels ----------------
__global__ void k_init(const float* __restrict__ wq, const float* __restrict__ w1,
                       const float* __restrict__ w2, const float* __restrict__ we)
{
    int i = blockIdx.x*256 + threadIdx.x;
    if (i < ZTOT) g_zero[i] = 0.f;
    if (i < 196608) g_wqkv_bf[i] = __float2bfloat16(wq[i]);
    if (i < 32768)  { g_wo1_bf[i] = __float2bfloat16(w1[i]);
                      g_wo2_bf[i] = __float2bfloat16(w2[i]); }
    if (i < NNT*64) g_we_bf[i] = __float2bfloat16(we[i]);
}

// grouped 1x1x1 conv via HMMA (unchanged)
__global__ __launch_bounds__(256) void k_convmma(
    const float* __restrict__ srcf, const __nv_bfloat16* __restrict__ srcb,
    const float* __restrict__ w, const float* __restrict__ bias,
    __nv_bfloat16* __restrict__ dst,
    const float* __restrict__ sin_s, const float* __restrict__ sin_q,
    float* __restrict__ sout_s, float* __restrict__ sout_q)
{
    __shared__ __align__(16) __nv_bfloat16 Ws[32][40];
    __shared__ __align__(16) __nv_bfloat16 Bs[32][520];
    __shared__ float sm[32], sr[32], bss[32];
    __shared__ float sst[8][32][2];
    int bg = blockIdx.y; int b = bg >> 3; int g = bg & 7;
    int n0 = blockIdx.x*512;
    int tid = threadIdx.x, lane = tid & 31, wid = tid >> 5;
    int cbase = b*CC + g*32;

    #pragma unroll
    for (int p = 0; p < 4; ++p) {
        int idx = p*256 + tid;
        Ws[idx & 31][idx >> 5] = __float2bfloat16(w[g*1024 + idx]);
    }
    if (tid < 32) {
        bss[tid] = bias[g*32 + tid];
        if (srcb) {
            float s = sin_s[cbase+tid], q = sin_q[cbase+tid];
            float m = s*(1.f/NNT);
            sm[tid] = m;
            sr[tid] = rsqrtf(q*(1.f/NNT) - m*m + 1e-5f);
        }
    }
    __syncthreads();

    if (srcf) {
        #pragma unroll
        for (int p = 0; p < 16; ++p) {
            int idx = p*256 + tid;
            int row = idx >> 7, cq = idx & 127;
            float4 v = *(const float4*)(srcf + (size_t)(cbase+row)*NNT + n0 + cq*4);
            *(__nv_bfloat162*)&Bs[row][cq*4]   = __floats2bfloat162_rn(v.x, v.y);
            *(__nv_bfloat162*)&Bs[row][cq*4+2] = __floats2bfloat162_rn(v.z, v.w);
        }
    } else {
        #pragma unroll
        for (int p = 0; p < 8; ++p) {
            int idx = p*256 + tid;
            int row = idx >> 6, sg = idx & 63;
            uint4 v = *(const uint4*)(srcb + (size_t)(cbase+row)*NNT + n0 + sg*8);
            const __nv_bfloat162* hh = (const __nv_bfloat162*)&v;
            float m = sm[row], r = sr[row];
            __nv_bfloat16 o[8];
            #pragma unroll
            for (int j = 0; j < 4; ++j) {
                float2 f = __bfloat1622float2(hh[j]);
                float fx = (f.x - m)*r; fx = fx >= 0.f ? fx : 0.01f*fx;
                float fy = (f.y - m)*r; fy = fy >= 0.f ? fy : 0.01f*fy;
                *(__nv_bfloat162*)&o[j*2] = __floats2bfloat162_rn(fx, fy);
            }
            *(uint4*)&Bs[row][sg*8] = *(uint4*)o;
        }
    }
    __syncthreads();

    float acc[2][8][4] = {};
    #pragma unroll
    for (int kk = 0; kk < 2; ++kk) {
        unsigned int af[2][4];
        #pragma unroll
        for (int mt = 0; mt < 2; ++mt)
            ldm_x4(af[mt], &Ws[mt*16 + (lane & 15)][kk*16 + (lane >> 4)*8]);
        unsigned int bfr[4][4];
        #pragma unroll
        for (int ng = 0; ng < 4; ++ng)
            ldm_x4_t(bfr[ng], &Bs[kk*16 + (lane & 15)][wid*64 + ng*16 + (lane >> 4)*8]);
        #pragma unroll
        for (int mt = 0; mt < 2; ++mt)
            #pragma unroll
            for (int nt = 0; nt < 8; ++nt)
                mma16816(acc[mt][nt], af[mt],
                         bfr[nt>>1][(nt&1)*2], bfr[nt>>1][(nt&1)*2+1]);
    }

    float ssum[2][2] = {}, ssq[2][2] = {};
    #pragma unroll
    for (int mt = 0; mt < 2; ++mt) {
        #pragma unroll
        for (int h = 0; h < 2; ++h) {
            int oc = mt*16 + (lane >> 2) + h*8;
            float bv = bss[oc];
            __nv_bfloat16* drow = dst + (size_t)(cbase+oc)*NNT + n0 + wid*64;
            #pragma unroll
            for (int nt = 0; nt < 8; ++nt) {
                float v0 = acc[mt][nt][h*2+0] + bv;
                float v1 = acc[mt][nt][h*2+1] + bv;
                *(__nv_bfloat162*)&drow[nt*8 + (lane & 3)*2] =
                    __floats2bfloat162_rn(v0, v1);
                ssum[mt][h] += v0 + v1;
                ssq [mt][h] += v0*v0 + v1*v1;
            }
        }
    }
    #pragma unroll
    for (int mt = 0; mt < 2; ++mt)
        #pragma unroll
        for (int h = 0; h < 2; ++h) {
            float s = ssum[mt][h], q = ssq[mt][h];
            s += __shfl_xor_sync(0xffffffffu, s, 1);
            q += __shfl_xor_sync(0xffffffffu, q, 1);
            s += __shfl_xor_sync(0xffffffffu, s, 2);
            q += __shfl_xor_sync(0xffffffffu, q, 2);
            if ((lane & 3) == 0) {
                int oc = mt*16 + (lane >> 2) + h*8;
                sst[wid][oc][0] = s;
                sst[wid][oc][1] = q;
            }
        }
    __syncthreads();
    if (tid < 64) {
        int oc = tid & 31, which = tid >> 5;
        float s = 0.f;
        #pragma unroll
        for (int ww = 0; ww < 8; ++ww) s += sst[ww][oc][which];
        atomicAdd(&(which ? sout_q : sout_s)[cbase+oc], s);
    }
}

// mega-fused LN kernel (unchanged from R13)
__global__ __launch_bounds__(256) void k_megaln(
    const float* __restrict__ x, const float* __restrict__ pos,
    const float* __restrict__ lg, const float* __restrict__ lb,
    const float* __restrict__ wp, float* __restrict__ dout)
{
    extern __shared__ float dsm[];
    float*  xs  = dsm;
    float2* st2 = (float2*)(dsm + 8448);
    float2* lgb = (float2*)(dsm + 8960);
    __nv_bfloat16* cs = (__nv_bfloat16*)(dsm + 9472);
    int tid = threadIdx.x, tx = tid & 31, ty = tid >> 5;
    int lane = tid & 31, w = tid >> 5;
    int n0 = blockIdx.x*32, b = blockIdx.y;
    {
        float s = g_zero[ZOFF_CS2S + b*256 + tid];
        float q = g_zero[ZOFF_CS2Q + b*256 + tid];
        float m = s*(1.f/NNT);
        st2[tid] = make_float2(m, rsqrtf(q*(1.f/NNT) - m*m + 1e-5f));
        lgb[tid] = make_float2(lg[tid], lb[tid]);
    }
    __syncthreads();
    for (int cc = ty; cc < 256; cc += 8) {
        size_t s = (size_t)(b*CC + cc)*NNT + n0 + tx;
        float xv = x[s];
        float2 st = st2[cc];
        float hv = (__bfloat162float(g_c2b[s]) - st.x)*st.y + xv;
        xs[cc*33 + tx] = xv;
        cs[cc*34 + tx] = __float2bfloat16(hv >= 0.f ? hv : 0.01f*hv);
    }
    __syncthreads();
    float pacc[8];
    #pragma unroll
    for (int j = 0; j < 8; ++j) pacc[j] = 0.f;
    for (int t8 = 0; t8 < 4; ++t8) {
        int tok = w + t8*8;
        const float* prow = pos + (size_t)(n0 + tok)*CC;
        float v1[8], v2[8];
        float s1 = 0.f, q1 = 0.f, s2 = 0.f, q2 = 0.f;
        #pragma unroll
        for (int q = 0; q < 4; ++q) {
            int c0 = lane*2 + q*64;
            float2 p2 = *(const float2*)(prow + c0);
            float ax = xs[c0*33 + tok] + p2.x;
            float ay = xs[(c0+1)*33 + tok] + p2.y;
            float dx = __bfloat162float(cs[c0*34 + tok]) + p2.x;
            float dy = __bfloat162float(cs[(c0+1)*34 + tok]) + p2.y;
            v1[q*2] = ax; v1[q*2+1] = ay;
            v2[q*2] = dx; v2[q*2+1] = dy;
            s1 += ax + ay; q1 += ax*ax + ay*ay;
            s2 += dx + dy; q2 += dx*dx + dy*dy;
        }
        #pragma unroll
        for (int o = 16; o; o >>= 1) {
            s1 += __shfl_xor_sync(0xffffffffu, s1, o);
            q1 += __shfl_xor_sync(0xffffffffu, q1, o);
            s2 += __shfl_xor_sync(0xffffffffu, s2, o);
            q2 += __shfl_xor_sync(0xffffffffu, q2, o);
        }
        float m1 = s1*(1.f/CC), r1 = rsqrtf(q1*(1.f/CC) - m1*m1 + 1e-5f);
        float m2 = s2*(1.f/CC), r2 = rsqrtf(q2*(1.f/CC) - m2*m2 + 1e-5f);
        float wpt = wp[n0 + tok];
        size_t gbase = ((size_t)b*NNT + n0 + tok)*CC;
        #pragma unroll
        for (int q = 0; q < 4; ++q) {
            int c0 = lane*2 + q*64;
            float4 gb = *(const float4*)(lgb + c0);
            float o1x = (v1[q*2]   - m1)*r1*gb.x + gb.y;
            float o1y = (v1[q*2+1] - m1)*r1*gb.z + gb.w;
            float o2x = (v2[q*2]   - m2)*r2*gb.x + gb.y;
            float o2y = (v2[q*2+1] - m2)*r2*gb.z + gb.w;
            *(__nv_bfloat162*)&g_xt_bf [gbase + c0] = __floats2bfloat162_rn(o1x, o1y);
            *(__nv_bfloat162*)&g_xct_bf[gbase + c0] = __floats2bfloat162_rn(o2x, o2y);
            xs[c0*33 + tok]     = o1x;
            xs[(c0+1)*33 + tok] = o1y;
            pacc[q*2]   += o2x*wpt;
            pacc[q*2+1] += o2y*wpt;
        }
    }
    __syncthreads();
    float* pws = (float*)cs;
    #pragma unroll
    for (int q = 0; q < 4; ++q) {
        int c0 = lane*2 + q*64;
        *(float2*)&pws[w*256 + c0] = make_float2(pacc[q*2], pacc[q*2+1]);
    }
    __syncthreads();
    {
        float s = 0.f;
        #pragma unroll
        for (int ww = 0; ww < 8; ++ww) s += pws[ww*256 + tid];
        atomicAdd(&g_zero[ZOFF_POOL + b*256 + tid], s);
    }
    for (int cc = ty; cc < 256; cc += 8)
        dout[(size_t)(b*CC + cc)*NNT + n0 + tx] = xs[cc*33 + tx];
}

// bf16 HMMA GEMM (unchanged from R13)
#define AS_(st,r,c) smem_mma[(size_t)(st)*9216 + (r)*72 + (c)]
#define BS_(st,r,c) smem_mma[18432 + (size_t)(st)*8704 + (r)*136 + (c)]
__global__ __launch_bounds__(256) void k_mma(
    const __nv_bfloat16* __restrict__ A, const __nv_bfloat16* __restrict__ A2,
    const __nv_bfloat16* __restrict__ Bw, const __nv_bfloat16* __restrict__ Bw2,
    const float* __restrict__ bias, const float* __restrict__ bias2,
    const float* __restrict__ gate,
    __nv_bfloat16* __restrict__ Cb, int Nld, int ldc, int doqss,
    float* __restrict__ dout, const float* __restrict__ gfin)
{
    extern __shared__ __nv_bfloat16 smem_mma[];
    int tid = threadIdx.x;
    int wid = tid >> 5, lane = tid & 31;
    int wm = wid >> 2;
    int wn = wid & 3;
    int m0 = blockIdx.y * 128;
    int n0 = blockIdx.x * 128;
    int coff = 0;
    const float* grow = nullptr;
    if (blockIdx.z == 1) {
        A = A2; Bw = Bw2; bias = bias2; coff = 128;
        grow = gate + (m0 / NNT)*CC;
    }

    float acc[4][4][4] = {};

    #pragma unroll
    for (int p = 0; p < 4; ++p) {
        int idx = p*256 + tid; int r = idx >> 3, sg = idx & 7;
        cpa16(&AS_(0, r, sg*8), A + (size_t)(m0 + r)*256 + sg*8);
    }
    #pragma unroll
    for (int p = 0; p < 4; ++p) {
        int idx = p*256 + tid; int r = idx >> 4, sg = idx & 15;
        cpa16(&BS_(0, r, sg*8), Bw + (size_t)r*Nld + n0 + sg*8);
    }
    cp_commit();

    for (int it = 0; it < 4; ++it) {
        int k0 = it*64, st = it & 1;
        if (it < 3) {
            int kn = k0 + 64, sn = st ^ 1;
            #pragma unroll
            for (int p = 0; p < 4; ++p) {
                int idx = p*256 + tid; int r = idx >> 3, sg = idx & 7;
                cpa16(&AS_(sn, r, sg*8), A + (size_t)(m0 + r)*256 + kn + sg*8);
            }
            #pragma unroll
            for (int p = 0; p < 4; ++p) {
                int idx = p*256 + tid; int r = idx >> 4, sg = idx & 15;
                cpa16(&BS_(sn, r, sg*8), Bw + (size_t)(kn + r)*Nld + n0 + sg*8);
            }
            cp_commit();
            cp_wait<1>();
        } else {
            cp_wait<0>();
        }
        __syncthreads();
        if (grow) {
            #pragma unroll
            for (int p = 0; p < 4; ++p) {
                int idx = p*256 + tid; int r = idx >> 3, sg = idx & 7;
                __nv_bfloat16* qp = &AS_(st, r, sg*8);
                #pragma unroll
                for (int j = 0; j < 8; ++j)
                    qp[j] = __float2bfloat16(__bfloat162float(qp[j])*grow[k0+sg*8+j]);
            }
            __syncthreads();
        }
        #pragma unroll
        for (int kk = 0; kk < 4; ++kk) {
            unsigned int af[4][4];
            #pragma unroll
            for (int mt = 0; mt < 4; ++mt)
                ldm_x4(af[mt], &AS_(st, wm*64 + mt*16 + (lane & 15), kk*16 + (lane >> 4)*8));
            unsigned int bfr[2][4];
            #pragma unroll
            for (int g2 = 0; g2 < 2; ++g2)
                ldm_x4_t(bfr[g2], &BS_(st, kk*16 + (lane & 15), wn*32 + g2*16 + (lane >> 4)*8));
            #pragma unroll
            for (int mt = 0; mt < 4; ++mt)
                #pragma unroll
                for (int nt = 0; nt < 4; ++nt)
                    mma16816(acc[mt][nt], af[mt],
                             bfr[nt>>1][(nt&1)*2], bfr[nt>>1][(nt&1)*2+1]);
        }
        __syncthreads();
    }
    if (doqss && n0 < 256) {
        int b = m0 / NNT;
        #pragma unroll
        for (int nt = 0; nt < 4; ++nt) {
            float s0 = 0.f, s1 = 0.f;
            #pragma unroll
            for (int mt = 0; mt < 4; ++mt) {
                #pragma unroll
                for (int h = 0; h < 2; ++h) {
                    float a0 = acc[mt][nt][h*2+0], a1 = acc[mt][nt][h*2+1];
                    s0 += a0*a0; s1 += a1*a1;
                }
            }
            #pragma unroll
            for (int o = 4; o <= 16; o <<= 1) {
                s0 += __shfl_xor_sync(0xffffffffu, s0, o);
                s1 += __shfl_xor_sync(0xffffffffu, s1, o);
            }
            if ((lane >> 2) == 0) {
                int col = n0 + wn*32 + nt*8 + (lane & 3)*2;
                atomicAdd(&g_zero[ZOFF_QSS + b*256 + col],   s0);
                atomicAdd(&g_zero[ZOFF_QSS + b*256 + col+1], s1);
            }
        }
    }
    if (doqss && n0 >= 256) {
        __nv_bfloat16* Cs = smem_mma;
        __nv_bfloat16* Es = smem_mma + 17408;
        int b = m0 / NNT;
        int n0t = m0 % NNT;
        int which = (n0 >= 512) ? 1 : 0;
        int dbase = n0 - 256 - which*256;
        #pragma unroll
        for (int mt = 0; mt < 4; ++mt) {
            int row0 = wm*64 + mt*16 + (lane >> 2);
            #pragma unroll
            for (int nt = 0; nt < 4; ++nt) {
                int col = wn*32 + nt*8 + (lane & 3)*2;
                #pragma unroll
                for (int h = 0; h < 2; ++h)
                    *(__nv_bfloat162*)&Cs[(row0 + h*8)*136 + col] =
                        __floats2bfloat162_rn(acc[mt][nt][h*2+0], acc[mt][nt][h*2+1]);
            }
        }
        #pragma unroll
        for (int p = 0; p < 4; ++p) {
            int idx = p*256 + tid; int r = idx >> 3, sg = idx & 7;
            *(uint4*)&Es[r*72 + sg*8] =
                *(const uint4*)(g_we_bf + (size_t)(n0t + r)*64 + sg*8);
        }
        __syncthreads();
        float a2[8][4] = {};
        #pragma unroll
        for (int kk = 0; kk < 128; kk += 16) {
            unsigned int af[4];
            ldm_x4_t(af, &Cs[(kk + (lane & 7) + ((lane >> 4) << 3))*136
                             + wid*16 + ((lane >> 3) & 1)*8]);
            unsigned int bfr[4][4];
            #pragma unroll
            for (int ng = 0; ng < 4; ++ng)
                ldm_x4_t(bfr[ng], &Es[(kk + (lane & 15))*72 + ng*16 + (lane >> 4)*8]);
            #pragma unroll
            for (int nt = 0; nt < 8; ++nt)
                mma16816(a2[nt], af, bfr[nt>>1][(nt&1)*2], bfr[nt>>1][(nt&1)*2+1]);
        }
        float* out = &g_zero[ZOFF_KP + which*32768 + b*16384];
        int m = dbase + wid*16 + (lane >> 2);
        #pragma unroll
        for (int nt = 0; nt < 8; ++nt) {
            int p = nt*8 + (lane & 3)*2;
            atomicAdd(&out[m*64 + p],       a2[nt][0]);
            atomicAdd(&out[m*64 + p + 1],   a2[nt][1]);
            atomicAdd(&out[(m+8)*64 + p],   a2[nt][2]);
            atomicAdd(&out[(m+8)*64 + p+1], a2[nt][3]);
        }
        return;
    }
    if (gfin) {
        float* ts = (float*)smem_mma;
        const int TS = 132;
        int b = m0 / NNT;
        int n0t = m0 % NNT;
        #pragma unroll
        for (int nt = 0; nt < 4; ++nt) {
            int ll = wn*32 + nt*8 + (lane & 3)*2;
            float gm0 = gfin[coff + ll], gm1 = gfin[coff + ll + 1];
            float b0 = bias[ll], b1 = bias[ll + 1];
            #pragma unroll
            for (int mt = 0; mt < 4; ++mt) {
                #pragma unroll
                for (int h = 0; h < 2; ++h) {
                    int rr = wm*64 + mt*16 + (lane >> 2) + h*8;
                    ts[ll*TS + rr]     = (acc[mt][nt][h*2+0] + b0)*gm0;
                    ts[(ll+1)*TS + rr] = (acc[mt][nt][h*2+1] + b1)*gm1;
                }
            }
        }
        __syncthreads();
        #pragma unroll
        for (int r = 0; r < 16; ++r) {
            int c = wid*16 + r;
            float* dp = dout + (size_t)(b*CC + coff + c)*NNT + n0t;
            float4 dv = *(float4*)(dp + lane*4);
            dv.x += ts[c*TS + lane*4 + 0];
            dv.y += ts[c*TS + lane*4 + 1];
            dv.z += ts[c*TS + lane*4 + 2];
            dv.w += ts[c*TS + lane*4 + 3];
            *(float4*)(dp + lane*4) = dv;
        }
        return;
    }
    #pragma unroll
    for (int mt = 0; mt < 4; ++mt) {
        int row0 = m0 + wm*64 + mt*16 + (lane >> 2);
        #pragma unroll
        for (int nt = 0; nt < 4; ++nt) {
            int col = wn*32 + nt*8 + (lane & 3)*2;
            #pragma unroll
            for (int h = 0; h < 2; ++h) {
                int r = row0 + h*8;
                float v0 = acc[mt][nt][h*2+0];
                float v1 = acc[mt][nt][h*2+1];
                if (bias) { v0 += bias[n0+col]; v1 += bias[n0+col+1]; }
                __nv_bfloat16* p = Cb + (size_t)r*ldc + coff + n0 + col;
                p[0] = __float2bfloat16(v0); p[1] = __float2bfloat16(v1);
            }
        }
    }
}

// fused attention: persistent K/V tiles, two 64-token tiles per block.
// dyn smem: sK|sV|sA|sB (bf16 64x72 each) | ss f32[64][68] | qr f32[64]
__global__ __launch_bounds__(256) void k_attn(
    const float* __restrict__ be, const float* __restrict__ temp,
    const float* __restrict__ bp, const float* __restrict__ w1,
    const float* __restrict__ w2)
{
    extern __shared__ char attn_smem[];
    __nv_bfloat16* sK = (__nv_bfloat16*)attn_smem;
    __nv_bfloat16* sV = (__nv_bfloat16*)(attn_smem + 9216);
    __nv_bfloat16* sA = (__nv_bfloat16*)(attn_smem + 18432);
    __nv_bfloat16* sB = (__nv_bfloat16*)(attn_smem + 27648);
    float* ss = (float*)(attn_smem + 36864);   // [64][68]
    float* qr = (float*)(attn_smem + 54272);   // [64]
    int bh = blockIdx.y; int b = bh >> 2, h = bh & 3;
    int tid = threadIdx.x;
    int wid = tid >> 5, lane = tid & 31;
    int wm = wid & 1, wn = wid >> 1;
    const float* kbase = &g_zero[ZOFF_KP + bh*4096];
    const float* vbase = &g_zero[ZOFF_VP + bh*4096];

    // fused CA gate (one block; block-uniform branch; ss used as scratch)
    if (blockIdx.x == 0 && blockIdx.y == 0) {
        float* ps = ss;
        float* hs = ps + 256;
        for (int b2 = 0; b2 < BB; ++b2) {
            ps[tid] = g_zero[ZOFF_POOL + b2*CC + tid] + bp[0];
            __syncthreads();
            if (tid < 64) {
                float a = 0.f;
                for (int c = 0; c < 256; ++c) a += ps[c]*w1[c*64 + tid];
                hs[tid] = fmaxf(a, 0.f);
            }
            __syncthreads();
            float a = 0.f;
            for (int j = 0; j < 64; ++j) a += hs[j]*w2[j*256 + tid];
            g_gate[b2*CC + tid] = 1.f/(1.f + expf(-a));
            __syncthreads();
        }
    }

    if (tid < 64)
        qr[tid] = 1.f / fmaxf(sqrtf(g_zero[ZOFF_QSS + b*256 + h*64 + tid]), 1e-12f);
    // persistent K-proj and V-proj tiles (+be), bf16
    #pragma unroll
    for (int v = 0; v < 4; ++v) {
        int i4 = v*256 + tid; int d = i4 >> 4, pp = (i4 & 15)*4;
        float4 kv = *(const float4*)(kbase + d*64 + pp);
        float4 vv = *(const float4*)(vbase + d*64 + pp);
        float bpv0 = be[pp], bpv1 = be[pp+1], bpv2 = be[pp+2], bpv3 = be[pp+3];
        sK[d*72 + pp]   = __float2bfloat16(kv.x + bpv0);
        sK[d*72 + pp+1] = __float2bfloat16(kv.y + bpv1);
        sK[d*72 + pp+2] = __float2bfloat16(kv.z + bpv2);
        sK[d*72 + pp+3] = __float2bfloat16(kv.w + bpv3);
        sV[d*72 + pp]   = __float2bfloat16(vv.x + bpv0);
        sV[d*72 + pp+1] = __float2bfloat16(vv.y + bpv1);
        sV[d*72 + pp+2] = __float2bfloat16(vv.z + bpv2);
        sV[d*72 + pp+3] = __float2bfloat16(vv.w + bpv3);
    }
    float ts = temp[h];
    __nv_bfloat16* sabase = g_sa_bf + (size_t)b*NNT*CC;

    for (int it = 0; it < 2; ++it) {
        int n0 = (blockIdx.x*2 + it)*64;
        // qn -> sA
        #pragma unroll
        for (int l = 0; l < 2; ++l) {
            int i8 = l*256 + tid; int r = i8 >> 3, sg = (i8 & 7)*8;
            uint4 v = *(const uint4*)(g_qkv_bf + ((size_t)(b*NNT + n0 + r))*768 + h*64 + sg);
            const __nv_bfloat162* hh = (const __nv_bfloat162*)&v;
            __nv_bfloat16 outv[8];
            #pragma unroll
            for (int j = 0; j < 4; ++j) {
                float2 f = __bfloat1622float2(hh[j]);
                outv[j*2]   = __float2bfloat16(f.x * qr[sg + j*2]);
                outv[j*2+1] = __float2bfloat16(f.y * qr[sg + j*2+1]);
            }
            *(uint4*)&sA[r*72 + sg] = *(uint4*)outv;
        }
        __syncthreads();
        // GEMM1: scores = qn @ kproj
        float acc1[2][2][4] = {};
        #pragma unroll
        for (int kk = 0; kk < 64; kk += 16) {
            unsigned int af[2][4];
            #pragma unroll
            for (int mt = 0; mt < 2; ++mt)
                ldm_x4(af[mt], &sA[(wm*32 + mt*16 + (lane & 15))*72 + kk + (lane >> 4)*8]);
            unsigned int bfr[4];
            ldm_x4_t(bfr, &sK[(kk + (lane & 15))*72 + wn*16 + (lane >> 4)*8]);
            #pragma unroll
            for (int mt = 0; mt < 2; ++mt)
                #pragma unroll
                for (int nt = 0; nt < 2; ++nt)
                    mma16816(acc1[mt][nt], af[mt], bfr[nt*2], bfr[nt*2+1]);
        }
        #pragma unroll
        for (int mt = 0; mt < 2; ++mt) {
            int r = wm*32 + mt*16 + (lane >> 2);
            #pragma unroll
            for (int nt = 0; nt < 2; ++nt) {
                int c = wn*16 + nt*8 + (lane & 3)*2;
                ss[r*68 + c]       = acc1[mt][nt][0]*ts;
                ss[r*68 + c+1]     = acc1[mt][nt][1]*ts;
                ss[(r+8)*68 + c]   = acc1[mt][nt][2]*ts;
                ss[(r+8)*68 + c+1] = acc1[mt][nt][3]*ts;
            }
        }
        __syncthreads();
        // softmax: 4 threads/row -> probs^T in sB[p][n]
        {
            int row = tid >> 2, g4 = (tid & 3)*16;
            float e[16];
            float mx = -1e30f;
            #pragma unroll
            for (int p = 0; p < 16; ++p) { e[p] = ss[row*68 + g4+p]; mx = fmaxf(mx, e[p]); }
            mx = fmaxf(mx, __shfl_xor_sync(0xffffffffu, mx, 1));
            mx = fmaxf(mx, __shfl_xor_sync(0xffffffffu, mx, 2));
            float sum = 0.f;
            #pragma unroll
            for (int p = 0; p < 16; ++p) { e[p] = __expf(e[p] - mx); sum += e[p]; }
            sum += __shfl_xor_sync(0xffffffffu, sum, 1);
            sum += __shfl_xor_sync(0xffffffffu, sum, 2);
            float inv = 1.f/sum;
            #pragma unroll
            for (int p = 0; p < 16; ++p)
                sB[(g4+p)*72 + row] = __float2bfloat16(e[p]*inv);
        }
        __syncthreads();
        // GEMM2: out[d][n] = v[d][p] @ probs^T[p][n]
        float acc2[2][2][4] = {};
        #pragma unroll
        for (int kk = 0; kk < 64; kk += 16) {
            unsigned int af[2][4];
            #pragma unroll
            for (int mt = 0; mt < 2; ++mt)
                ldm_x4(af[mt], &sV[(wm*32 + mt*16 + (lane & 15))*72 + kk + (lane >> 4)*8]);
            unsigned int bfr[4];
            ldm_x4_t(bfr, &sB[(kk + (lane & 15))*72 + wn*16 + (lane >> 4)*8]);
            #pragma unroll
            for (int mt = 0; mt < 2; ++mt)
                #pragma unroll
                for (int nt = 0; nt < 2; ++nt)
                    mma16816(acc2[mt][nt], af[mt], bfr[nt*2], bfr[nt*2+1]);
        }
        #pragma unroll
        for (int mt = 0; mt < 2; ++mt) {
            int d0 = wm*32 + mt*16 + (lane >> 2);
            #pragma unroll
            for (int nt = 0; nt < 2; ++nt) {
                int nc = n0 + wn*16 + nt*8 + (lane & 3)*2;
                *(__nv_bfloat162*)&sabase[(size_t)(d0*4 + h)*NNT + nc] =
                    __floats2bfloat162_rn(acc2[mt][nt][0], acc2[mt][nt][1]);
                *(__nv_bfloat162*)&sabase[(size_t)((d0+8)*4 + h)*NNT + nc] =
                    __floats2bfloat162_rn(acc2[mt][nt][2], acc2[mt][nt][3]);
            }
        }
        __syncthreads();
    }
}

// ---------------- launch ----------------
extern "C" void kernel_launch(void* const* d_in, const int* in_sizes, int n_in,
                              void* d_out, int out_size)
{
    const float* x      = (const float*)d_in[0];
    const float* pos    = (const float*)d_in[1];
    const float* ln_g   = (const float*)d_in[2];
    const float* ln_b   = (const float*)d_in[3];
    const float* gamma  = (const float*)d_in[4];
    const float* temp2  = (const float*)d_in[5];
    const float* w_qkv  = (const float*)d_in[6];
    const float* w_e    = (const float*)d_in[7];
    const float* b_e    = (const float*)d_in[8];
    const float* w_pool = (const float*)d_in[9];
    const float* b_pool = (const float*)d_in[10];
    const float* w_fc1  = (const float*)d_in[11];
    const float* w_fc2  = (const float*)d_in[12];
    const float* b_out1 = (const float*)d_in[14];
    const float* b_out2 = (const float*)d_in[16];
    const float* w_c1   = (const float*)d_in[17];
    const float* b_c1   = (const float*)d_in[18];
    const float* w_c2   = (const float*)d_in[19];
    const float* b_c2   = (const float*)d_in[20];

    __nv_bfloat16 *p_h1b, *p_c2b, *p_xtbf, *p_xctbf, *p_sabf;
    __nv_bfloat16 *p_wq, *p_w1, *p_w2, *p_qkvbf;
    float *p_gate, *p_zero;
    cudaGetSymbolAddress((void**)&p_h1b,   g_h1b);
    cudaGetSymbolAddress((void**)&p_c2b,   g_c2b);
    cudaGetSymbolAddress((void**)&p_xtbf,  g_xt_bf);
    cudaGetSymbolAddress((void**)&p_xctbf, g_xct_bf);
    cudaGetSymbolAddress((void**)&p_qkvbf, g_qkv_bf);
    cudaGetSymbolAddress((void**)&p_sabf,  g_sa_bf);
    cudaGetSymbolAddress((void**)&p_wq,    g_wqkv_bf);
    cudaGetSymbolAddress((void**)&p_w1,    g_wo1_bf);
    cudaGetSymbolAddress((void**)&p_w2,    g_wo2_bf);
    cudaGetSymbolAddress((void**)&p_gate,  g_gate);
    cudaGetSymbolAddress((void**)&p_zero,  g_zero);

    static int s_attr_done = 0;
    if (!s_attr_done) {
        cudaFuncSetAttribute(k_megaln,
            cudaFuncAttributeMaxDynamicSharedMemorySize, 55296);
        cudaFuncSetAttribute(k_mma,
            cudaFuncAttributeMaxDynamicSharedMemorySize, 71680);
        cudaFuncSetAttribute(k_attn,
            cudaFuncAttributeMaxDynamicSharedMemorySize, 55296);
        s_attr_done = 1;
    }

    k_init <<<3456, 256>>>(w_qkv, (const float*)d_in[13],
                           (const float*)d_in[15], w_e);
    // MHCResBlock: grouped convs via HMMA with fused stats
    k_convmma<<<dim3(27,16), 256>>>(x, (const __nv_bfloat16*)0, w_c1, b_c1, p_h1b,
                                    (const float*)0, (const float*)0,
                                    p_zero + ZOFF_CS1S, p_zero + ZOFF_CS1Q);
    k_convmma<<<dim3(27,16), 256>>>((const float*)0, p_h1b, w_c2, b_c2, p_c2b,
                                    p_zero + ZOFF_CS1S, p_zero + ZOFF_CS1Q,
                                    p_zero + ZOFF_CS2S, p_zero + ZOFF_CS2Q);
    // mega-fused transpose + xc + double-LN + pool + d_out(x_n)
    k_megaln<<<dim3(432, BB), 256, 55296>>>(x, pos, ln_g, ln_b, w_pool,
                                            (float*)d_out);
    // qkv (pipelined bf16 HMMA, fused q sum-squares + fused K/V low-rank proj)
    k_mma  <<<dim3(6,216,1), 256, 71680>>>(p_xtbf, (const __nv_bfloat16*)0, p_wq,
                                    (const __nv_bfloat16*)0, (const float*)0,
                                    (const float*)0, (const float*)0,
                                    p_qkvbf, 768, 768, 1,
                                    (float*)0, (const float*)0);
    // spatial attention: 2 token tiles/block, persistent K/V (+ fused CA gate)
    k_attn <<<dim3(108, BB*NHH), 256, 54528>>>(b_e, temp2, b_pool, w_fc1, w_fc2);
    // both output projections with fused gamma-residual into d_out
    k_mma  <<<dim3(1,216,2), 256, 71680>>>(p_sabf, p_xctbf, p_w1, p_w2,
                                    b_out1, b_out2, p_gate,
                                    (__nv_bfloat16*)0, 128, 256, 0,
                                    (float*)d_out, gamma);
}

// round 15
// speedup vs baseline: 1.0172x; 1.0172x over previous
#include <cuda_runtime.h>
#include <cuda_bf16.h>
#include <cstdint>
#include <math.h>

#define BB 2
#define CC 256
#define NNT 13824
#define NHH 4
#define MTOT (BB*NNT)

// ---------------- scratch ----------------
__device__ __nv_bfloat16 g_h1b[BB*CC*NNT];
__device__ __nv_bfloat16 g_c2b[BB*CC*NNT];
__device__ __nv_bfloat16 g_xt_bf [BB*NNT*CC];
__device__ __nv_bfloat16 g_xct_bf[BB*NNT*CC];
__device__ __nv_bfloat16 g_qkv_bf[(size_t)BB*NNT*768];
__device__ __nv_bfloat16 g_sa_bf [BB*NNT*CC];
__device__ __nv_bfloat16 g_wqkv_bf[256*768];
__device__ __nv_bfloat16 g_wo1_bf [256*128];
__device__ __nv_bfloat16 g_wo2_bf [256*128];
__device__ __nv_bfloat16 g_we_bf  [NNT*64];
#define ZOFF_POOL 0
#define ZOFF_QSS  512
#define ZOFF_CS1S 1024
#define ZOFF_CS1Q 1536
#define ZOFF_CS2S 2048
#define ZOFF_CS2Q 2560
#define ZOFF_KP   3072
#define ZOFF_VP   35840
#define ZTOT      68608
__device__ float g_zero[ZTOT];
__device__ float g_gate[BB*CC];

// ---------------- asm helpers ----------------
__device__ __forceinline__ void ldm_x4(unsigned int (&r)[4], const void* p) {
    unsigned int a = (unsigned int)__cvta_generic_to_shared(p);
    asm volatile("ldmatrix.sync.aligned.m8n8.x4.shared.b16 {%0,%1,%2,%3}, [%4];"
        : "=r"(r[0]),"=r"(r[1]),"=r"(r[2]),"=r"(r[3]) : "r"(a));
}
__device__ __forceinline__ void ldm_x4_t(unsigned int (&r)[4], const void* p) {
    unsigned int a = (unsigned int)__cvta_generic_to_shared(p);
    asm volatile("ldmatrix.sync.aligned.m8n8.x4.trans.shared.b16 {%0,%1,%2,%3}, [%4];"
        : "=r"(r[0]),"=r"(r[1]),"=r"(r[2]),"=r"(r[3]) : "r"(a));
}
__device__ __forceinline__ void mma16816(float (&d)[4], const unsigned int (&a)[4],
                                         unsigned int b0, unsigned int b1) {
    asm volatile("mma.sync.aligned.m16n8k16.row.col.f32.bf16.bf16.f32 "
        "{%0,%1,%2,%3},{%4,%5,%6,%7},{%8,%9},{%0,%1,%2,%3};"
        : "+f"(d[0]),"+f"(d[1]),"+f"(d[2]),"+f"(d[3])
        : "r"(a[0]),"r"(a[1]),"r"(a[2]),"r"(a[3]),"r"(b0),"r"(b1));
}
__device__ __forceinline__ void cpa16(void* dst, const void* src) {
    unsigned int d = (unsigned int)__cvta_generic_to_shared(dst);
    asm volatile("cp.async.cg.shared.global [%0], [%1], 16;" :: "r"(d), "l"(src));
}
__device__ __forceinline__ void cp_commit() { asm volatile("cp.async.commit_group;"); }
template<int N> __device__ __forceinline__ void cp_wait() {
    asm volatile("cp.async.wait_group %0;" :: "n"(N));
}

// ---------------- kernels ----------------
__global__ void k_init(const float* __restrict__ wq, const float* __restrict__ w1,
                       const float* __restrict__ w2, const float* __restrict__ we)
{
    int i = blockIdx.x*256 + threadIdx.x;
    if (i < ZTOT) g_zero[i] = 0.f;
    if (i < 196608) g_wqkv_bf[i] = __float2bfloat16(wq[i]);
    if (i < 32768)  { g_wo1_bf[i] = __float2bfloat16(w1[i]);
                      g_wo2_bf[i] = __float2bfloat16(w2[i]); }
    if (i < NNT*64) g_we_bf[i] = __float2bfloat16(we[i]);
}

// grouped 1x1x1 conv via HMMA (unchanged)
__global__ __launch_bounds__(256) void k_convmma(
    const float* __restrict__ srcf, const __nv_bfloat16* __restrict__ srcb,
    const float* __restrict__ w, const float* __restrict__ bias,
    __nv_bfloat16* __restrict__ dst,
    const float* __restrict__ sin_s, const float* __restrict__ sin_q,
    float* __restrict__ sout_s, float* __restrict__ sout_q)
{
    __shared__ __align__(16) __nv_bfloat16 Ws[32][40];
    __shared__ __align__(16) __nv_bfloat16 Bs[32][520];
    __shared__ float sm[32], sr[32], bss[32];
    __shared__ float sst[8][32][2];
    int bg = blockIdx.y; int b = bg >> 3; int g = bg & 7;
    int n0 = blockIdx.x*512;
    int tid = threadIdx.x, lane = tid & 31, wid = tid >> 5;
    int cbase = b*CC + g*32;

    #pragma unroll
    for (int p = 0; p < 4; ++p) {
        int idx = p*256 + tid;
        Ws[idx & 31][idx >> 5] = __float2bfloat16(w[g*1024 + idx]);
    }
    if (tid < 32) {
        bss[tid] = bias[g*32 + tid];
        if (srcb) {
            float s = sin_s[cbase+tid], q = sin_q[cbase+tid];
            float m = s*(1.f/NNT);
            sm[tid] = m;
            sr[tid] = rsqrtf(q*(1.f/NNT) - m*m + 1e-5f);
        }
    }
    __syncthreads();

    if (srcf) {
        #pragma unroll
        for (int p = 0; p < 16; ++p) {
            int idx = p*256 + tid;
            int row = idx >> 7, cq = idx & 127;
            float4 v = *(const float4*)(srcf + (size_t)(cbase+row)*NNT + n0 + cq*4);
            *(__nv_bfloat162*)&Bs[row][cq*4]   = __floats2bfloat162_rn(v.x, v.y);
            *(__nv_bfloat162*)&Bs[row][cq*4+2] = __floats2bfloat162_rn(v.z, v.w);
        }
    } else {
        #pragma unroll
        for (int p = 0; p < 8; ++p) {
            int idx = p*256 + tid;
            int row = idx >> 6, sg = idx & 63;
            uint4 v = *(const uint4*)(srcb + (size_t)(cbase+row)*NNT + n0 + sg*8);
            const __nv_bfloat162* hh = (const __nv_bfloat162*)&v;
            float m = sm[row], r = sr[row];
            __nv_bfloat16 o[8];
            #pragma unroll
            for (int j = 0; j < 4; ++j) {
                float2 f = __bfloat1622float2(hh[j]);
                float fx = (f.x - m)*r; fx = fx >= 0.f ? fx : 0.01f*fx;
                float fy = (f.y - m)*r; fy = fy >= 0.f ? fy : 0.01f*fy;
                *(__nv_bfloat162*)&o[j*2] = __floats2bfloat162_rn(fx, fy);
            }
            *(uint4*)&Bs[row][sg*8] = *(uint4*)o;
        }
    }
    __syncthreads();

    float acc[2][8][4] = {};
    #pragma unroll
    for (int kk = 0; kk < 2; ++kk) {
        unsigned int af[2][4];
        #pragma unroll
        for (int mt = 0; mt < 2; ++mt)
            ldm_x4(af[mt], &Ws[mt*16 + (lane & 15)][kk*16 + (lane >> 4)*8]);
        unsigned int bfr[4][4];
        #pragma unroll
        for (int ng = 0; ng < 4; ++ng)
            ldm_x4_t(bfr[ng], &Bs[kk*16 + (lane & 15)][wid*64 + ng*16 + (lane >> 4)*8]);
        #pragma unroll
        for (int mt = 0; mt < 2; ++mt)
            #pragma unroll
            for (int nt = 0; nt < 8; ++nt)
                mma16816(acc[mt][nt], af[mt],
                         bfr[nt>>1][(nt&1)*2], bfr[nt>>1][(nt&1)*2+1]);
    }

    float ssum[2][2] = {}, ssq[2][2] = {};
    #pragma unroll
    for (int mt = 0; mt < 2; ++mt) {
        #pragma unroll
        for (int h = 0; h < 2; ++h) {
            int oc = mt*16 + (lane >> 2) + h*8;
            float bv = bss[oc];
            __nv_bfloat16* drow = dst + (size_t)(cbase+oc)*NNT + n0 + wid*64;
            #pragma unroll
            for (int nt = 0; nt < 8; ++nt) {
                float v0 = acc[mt][nt][h*2+0] + bv;
                float v1 = acc[mt][nt][h*2+1] + bv;
                *(__nv_bfloat162*)&drow[nt*8 + (lane & 3)*2] =
                    __floats2bfloat162_rn(v0, v1);
                ssum[mt][h] += v0 + v1;
                ssq [mt][h] += v0*v0 + v1*v1;
            }
        }
    }
    #pragma unroll
    for (int mt = 0; mt < 2; ++mt)
        #pragma unroll
        for (int h = 0; h < 2; ++h) {
            float s = ssum[mt][h], q = ssq[mt][h];
            s += __shfl_xor_sync(0xffffffffu, s, 1);
            q += __shfl_xor_sync(0xffffffffu, q, 1);
            s += __shfl_xor_sync(0xffffffffu, s, 2);
            q += __shfl_xor_sync(0xffffffffu, q, 2);
            if ((lane & 3) == 0) {
                int oc = mt*16 + (lane >> 2) + h*8;
                sst[wid][oc][0] = s;
                sst[wid][oc][1] = q;
            }
        }
    __syncthreads();
    if (tid < 64) {
        int oc = tid & 31, which = tid >> 5;
        float s = 0.f;
        #pragma unroll
        for (int ww = 0; ww < 8; ++ww) s += sst[ww][oc][which];
        atomicAdd(&(which ? sout_q : sout_s)[cbase+oc], s);
    }
}

// mega-fused LN kernel; d_out written with streaming hint (evict-first).
__global__ __launch_bounds__(256) void k_megaln(
    const float* __restrict__ x, const float* __restrict__ pos,
    const float* __restrict__ lg, const float* __restrict__ lb,
    const float* __restrict__ wp, float* __restrict__ dout)
{
    extern __shared__ float dsm[];
    float*  xs  = dsm;
    float2* st2 = (float2*)(dsm + 8448);
    float2* lgb = (float2*)(dsm + 8960);
    __nv_bfloat16* cs = (__nv_bfloat16*)(dsm + 9472);
    int tid = threadIdx.x, tx = tid & 31, ty = tid >> 5;
    int lane = tid & 31, w = tid >> 5;
    int n0 = blockIdx.x*32, b = blockIdx.y;
    {
        float s = g_zero[ZOFF_CS2S + b*256 + tid];
        float q = g_zero[ZOFF_CS2Q + b*256 + tid];
        float m = s*(1.f/NNT);
        st2[tid] = make_float2(m, rsqrtf(q*(1.f/NNT) - m*m + 1e-5f));
        lgb[tid] = make_float2(lg[tid], lb[tid]);
    }
    __syncthreads();
    for (int cc = ty; cc < 256; cc += 8) {
        size_t s = (size_t)(b*CC + cc)*NNT + n0 + tx;
        float xv = x[s];
        float2 st = st2[cc];
        float hv = (__bfloat162float(g_c2b[s]) - st.x)*st.y + xv;
        xs[cc*33 + tx] = xv;
        cs[cc*34 + tx] = __float2bfloat16(hv >= 0.f ? hv : 0.01f*hv);
    }
    __syncthreads();
    float pacc[8];
    #pragma unroll
    for (int j = 0; j < 8; ++j) pacc[j] = 0.f;
    for (int t8 = 0; t8 < 4; ++t8) {
        int tok = w + t8*8;
        const float* prow = pos + (size_t)(n0 + tok)*CC;
        float v1[8], v2[8];
        float s1 = 0.f, q1 = 0.f, s2 = 0.f, q2 = 0.f;
        #pragma unroll
        for (int q = 0; q < 4; ++q) {
            int c0 = lane*2 + q*64;
            float2 p2 = *(const float2*)(prow + c0);
            float ax = xs[c0*33 + tok] + p2.x;
            float ay = xs[(c0+1)*33 + tok] + p2.y;
            float dx = __bfloat162float(cs[c0*34 + tok]) + p2.x;
            float dy = __bfloat162float(cs[(c0+1)*34 + tok]) + p2.y;
            v1[q*2] = ax; v1[q*2+1] = ay;
            v2[q*2] = dx; v2[q*2+1] = dy;
            s1 += ax + ay; q1 += ax*ax + ay*ay;
            s2 += dx + dy; q2 += dx*dx + dy*dy;
        }
        #pragma unroll
        for (int o = 16; o; o >>= 1) {
            s1 += __shfl_xor_sync(0xffffffffu, s1, o);
            q1 += __shfl_xor_sync(0xffffffffu, q1, o);
            s2 += __shfl_xor_sync(0xffffffffu, s2, o);
            q2 += __shfl_xor_sync(0xffffffffu, q2, o);
        }
        float m1 = s1*(1.f/CC), r1 = rsqrtf(q1*(1.f/CC) - m1*m1 + 1e-5f);
        float m2 = s2*(1.f/CC), r2 = rsqrtf(q2*(1.f/CC) - m2*m2 + 1e-5f);
        float wpt = wp[n0 + tok];
        size_t gbase = ((size_t)b*NNT + n0 + tok)*CC;
        #pragma unroll
        for (int q = 0; q < 4; ++q) {
            int c0 = lane*2 + q*64;
            float4 gb = *(const float4*)(lgb + c0);
            float o1x = (v1[q*2]   - m1)*r1*gb.x + gb.y;
            float o1y = (v1[q*2+1] - m1)*r1*gb.z + gb.w;
            float o2x = (v2[q*2]   - m2)*r2*gb.x + gb.y;
            float o2y = (v2[q*2+1] - m2)*r2*gb.z + gb.w;
            *(__nv_bfloat162*)&g_xt_bf [gbase + c0] = __floats2bfloat162_rn(o1x, o1y);
            *(__nv_bfloat162*)&g_xct_bf[gbase + c0] = __floats2bfloat162_rn(o2x, o2y);
            xs[c0*33 + tok]     = o1x;
            xs[(c0+1)*33 + tok] = o1y;
            pacc[q*2]   += o2x*wpt;
            pacc[q*2+1] += o2y*wpt;
        }
    }
    __syncthreads();
    float* pws = (float*)cs;
    #pragma unroll
    for (int q = 0; q < 4; ++q) {
        int c0 = lane*2 + q*64;
        *(float2*)&pws[w*256 + c0] = make_float2(pacc[q*2], pacc[q*2+1]);
    }
    __syncthreads();
    {
        float s = 0.f;
        #pragma unroll
        for (int ww = 0; ww < 8; ++ww) s += pws[ww*256 + tid];
        atomicAdd(&g_zero[ZOFF_POOL + b*256 + tid], s);
    }
    for (int cc = ty; cc < 256; cc += 8)
        __stcs(&dout[(size_t)(b*CC + cc)*NNT + n0 + tx], xs[cc*33 + tx]);
}

// bf16 HMMA GEMM, K=64 chunks, cp.async double buffering, dynamic smem.
#define AS_(st,r,c) smem_mma[(size_t)(st)*9216 + (r)*72 + (c)]
#define BS_(st,r,c) smem_mma[18432 + (size_t)(st)*8704 + (r)*136 + (c)]
__global__ __launch_bounds__(256) void k_mma(
    const __nv_bfloat16* __restrict__ A, const __nv_bfloat16* __restrict__ A2,
    const __nv_bfloat16* __restrict__ Bw, const __nv_bfloat16* __restrict__ Bw2,
    const float* __restrict__ bias, const float* __restrict__ bias2,
    const float* __restrict__ gate,
    __nv_bfloat16* __restrict__ Cb, int Nld, int ldc, int doqss,
    float* __restrict__ dout, const float* __restrict__ gfin)
{
    extern __shared__ __nv_bfloat16 smem_mma[];
    int tid = threadIdx.x;
    int wid = tid >> 5, lane = tid & 31;
    int wm = wid >> 2;
    int wn = wid & 3;
    int m0 = blockIdx.y * 128;
    int n0 = blockIdx.x * 128;
    int coff = 0;
    const float* grow = nullptr;
    if (blockIdx.z == 1) {
        A = A2; Bw = Bw2; bias = bias2; coff = 128;
        grow = gate + (m0 / NNT)*CC;
    }

    float acc[4][4][4] = {};

    #pragma unroll
    for (int p = 0; p < 4; ++p) {
        int idx = p*256 + tid; int r = idx >> 3, sg = idx & 7;
        cpa16(&AS_(0, r, sg*8), A + (size_t)(m0 + r)*256 + sg*8);
    }
    #pragma unroll
    for (int p = 0; p < 4; ++p) {
        int idx = p*256 + tid; int r = idx >> 4, sg = idx & 15;
        cpa16(&BS_(0, r, sg*8), Bw + (size_t)r*Nld + n0 + sg*8);
    }
    cp_commit();

    for (int it = 0; it < 4; ++it) {
        int k0 = it*64, st = it & 1;
        if (it < 3) {
            int kn = k0 + 64, sn = st ^ 1;
            #pragma unroll
            for (int p = 0; p < 4; ++p) {
                int idx = p*256 + tid; int r = idx >> 3, sg = idx & 7;
                cpa16(&AS_(sn, r, sg*8), A + (size_t)(m0 + r)*256 + kn + sg*8);
            }
            #pragma unroll
            for (int p = 0; p < 4; ++p) {
                int idx = p*256 + tid; int r = idx >> 4, sg = idx & 15;
                cpa16(&BS_(sn, r, sg*8), Bw + (size_t)(kn + r)*Nld + n0 + sg*8);
            }
            cp_commit();
            cp_wait<1>();
        } else {
            cp_wait<0>();
        }
        __syncthreads();
        if (grow) {
            #pragma unroll
            for (int p = 0; p < 4; ++p) {
                int idx = p*256 + tid; int r = idx >> 3, sg = idx & 7;
                __nv_bfloat16* qp = &AS_(st, r, sg*8);
                #pragma unroll
                for (int j = 0; j < 8; ++j)
                    qp[j] = __float2bfloat16(__bfloat162float(qp[j])*grow[k0+sg*8+j]);
            }
            __syncthreads();
        }
        #pragma unroll
        for (int kk = 0; kk < 4; ++kk) {
            unsigned int af[4][4];
            #pragma unroll
            for (int mt = 0; mt < 4; ++mt)
                ldm_x4(af[mt], &AS_(st, wm*64 + mt*16 + (lane & 15), kk*16 + (lane >> 4)*8));
            unsigned int bfr[2][4];
            #pragma unroll
            for (int g2 = 0; g2 < 2; ++g2)
                ldm_x4_t(bfr[g2], &BS_(st, kk*16 + (lane & 15), wn*32 + g2*16 + (lane >> 4)*8));
            #pragma unroll
            for (int mt = 0; mt < 4; ++mt)
                #pragma unroll
                for (int nt = 0; nt < 4; ++nt)
                    mma16816(acc[mt][nt], af[mt],
                             bfr[nt>>1][(nt&1)*2], bfr[nt>>1][(nt&1)*2+1]);
        }
        __syncthreads();
    }
    if (doqss && n0 < 256) {
        int b = m0 / NNT;
        #pragma unroll
        for (int nt = 0; nt < 4; ++nt) {
            float s0 = 0.f, s1 = 0.f;
            #pragma unroll
            for (int mt = 0; mt < 4; ++mt) {
                #pragma unroll
                for (int h = 0; h < 2; ++h) {
                    float a0 = acc[mt][nt][h*2+0], a1 = acc[mt][nt][h*2+1];
                    s0 += a0*a0; s1 += a1*a1;
                }
            }
            #pragma unroll
            for (int o = 4; o <= 16; o <<= 1) {
                s0 += __shfl_xor_sync(0xffffffffu, s0, o);
                s1 += __shfl_xor_sync(0xffffffffu, s1, o);
            }
            if ((lane >> 2) == 0) {
                int col = n0 + wn*32 + nt*8 + (lane & 3)*2;
                atomicAdd(&g_zero[ZOFF_QSS + b*256 + col],   s0);
                atomicAdd(&g_zero[ZOFF_QSS + b*256 + col+1], s1);
            }
        }
    }
    if (doqss && n0 >= 256) {
        __nv_bfloat16* Cs = smem_mma;
        __nv_bfloat16* Es = smem_mma + 17408;
        int b = m0 / NNT;
        int n0t = m0 % NNT;
        int which = (n0 >= 512) ? 1 : 0;
        int dbase = n0 - 256 - which*256;
        #pragma unroll
        for (int mt = 0; mt < 4; ++mt) {
            int row0 = wm*64 + mt*16 + (lane >> 2);
            #pragma unroll
            for (int nt = 0; nt < 4; ++nt) {
                int col = wn*32 + nt*8 + (lane & 3)*2;
                #pragma unroll
                for (int h = 0; h < 2; ++h)
                    *(__nv_bfloat162*)&Cs[(row0 + h*8)*136 + col] =
                        __floats2bfloat162_rn(acc[mt][nt][h*2+0], acc[mt][nt][h*2+1]);
            }
        }
        #pragma unroll
        for (int p = 0; p < 4; ++p) {
            int idx = p*256 + tid; int r = idx >> 3, sg = idx & 7;
            *(uint4*)&Es[r*72 + sg*8] =
                *(const uint4*)(g_we_bf + (size_t)(n0t + r)*64 + sg*8);
        }
        __syncthreads();
        float a2[8][4] = {};
        #pragma unroll
        for (int kk = 0; kk < 128; kk += 16) {
            unsigned int af[4];
            ldm_x4_t(af, &Cs[(kk + (lane & 7) + ((lane >> 4) << 3))*136
                             + wid*16 + ((lane >> 3) & 1)*8]);
            unsigned int bfr[4][4];
            #pragma unroll
            for (int ng = 0; ng < 4; ++ng)
                ldm_x4_t(bfr[ng], &Es[(kk + (lane & 15))*72 + ng*16 + (lane >> 4)*8]);
            #pragma unroll
            for (int nt = 0; nt < 8; ++nt)
                mma16816(a2[nt], af, bfr[nt>>1][(nt&1)*2], bfr[nt>>1][(nt&1)*2+1]);
        }
        float* out = &g_zero[ZOFF_KP + which*32768 + b*16384];
        int m = dbase + wid*16 + (lane >> 2);
        #pragma unroll
        for (int nt = 0; nt < 8; ++nt) {
            int p = nt*8 + (lane & 3)*2;
            atomicAdd(&out[m*64 + p],       a2[nt][0]);
            atomicAdd(&out[m*64 + p + 1],   a2[nt][1]);
            atomicAdd(&out[(m+8)*64 + p],   a2[nt][2]);
            atomicAdd(&out[(m+8)*64 + p+1], a2[nt][3]);
        }
        return;
    }
    if (gfin) {
        // single-pass transpose epilogue; streaming RMW on d_out
        float* ts = (float*)smem_mma;
        const int TS = 132;
        int b = m0 / NNT;
        int n0t = m0 % NNT;
        #pragma unroll
        for (int nt = 0; nt < 4; ++nt) {
            int ll = wn*32 + nt*8 + (lane & 3)*2;
            float gm0 = gfin[coff + ll], gm1 = gfin[coff + ll + 1];
            float b0 = bias[ll], b1 = bias[ll + 1];
            #pragma unroll
            for (int mt = 0; mt < 4; ++mt) {
                #pragma unroll
                for (int h = 0; h < 2; ++h) {
                    int rr = wm*64 + mt*16 + (lane >> 2) + h*8;
                    ts[ll*TS + rr]     = (acc[mt][nt][h*2+0] + b0)*gm0;
                    ts[(ll+1)*TS + rr] = (acc[mt][nt][h*2+1] + b1)*gm1;
                }
            }
        }
        __syncthreads();
        #pragma unroll
        for (int r = 0; r < 16; ++r) {
            int c = wid*16 + r;
            float* dp = dout + (size_t)(b*CC + coff + c)*NNT + n0t;
            float4 dv = __ldcs((const float4*)(dp + lane*4));
            dv.x += ts[c*TS + lane*4 + 0];
            dv.y += ts[c*TS + lane*4 + 1];
            dv.z += ts[c*TS + lane*4 + 2];
            dv.w += ts[c*TS + lane*4 + 3];
            __stcs((float4*)(dp + lane*4), dv);
        }
        return;
    }
    #pragma unroll
    for (int mt = 0; mt < 4; ++mt) {
        int row0 = m0 + wm*64 + mt*16 + (lane >> 2);
        #pragma unroll
        for (int nt = 0; nt < 4; ++nt) {
            int col = wn*32 + nt*8 + (lane & 3)*2;
            #pragma unroll
            for (int h = 0; h < 2; ++h) {
                int r = row0 + h*8;
                float v0 = acc[mt][nt][h*2+0];
                float v1 = acc[mt][nt][h*2+1];
                if (bias) { v0 += bias[n0+col]; v1 += bias[n0+col+1]; }
                __nv_bfloat16* p = Cb + (size_t)r*ldc + coff + n0 + col;
                p[0] = __float2bfloat16(v0); p[1] = __float2bfloat16(v1);
            }
        }
    }
}

// fused attention tile (R13 version); block (0,0) also computes the CA gate.
__global__ __launch_bounds__(256) void k_attn(
    const float* __restrict__ be, const float* __restrict__ temp,
    const float* __restrict__ bp, const float* __restrict__ w1,
    const float* __restrict__ w2)
{
    int bh = blockIdx.y; int b = bh >> 2, h = bh & 3;
    int n0 = blockIdx.x*64;
    __shared__ __align__(16) __nv_bfloat16 sA[64][72];
    __shared__ __align__(16) __nv_bfloat16 sB[64][72];
    __shared__ float ss[64][68];
    __shared__ float qr[64];
    int tid = threadIdx.x;
    int wid = tid >> 5, lane = tid & 31;
    int wm = wid & 1, wn = wid >> 1;
    const float* kbase = &g_zero[ZOFF_KP + bh*4096];
    const float* vbase = &g_zero[ZOFF_VP + bh*4096];

    if (blockIdx.x == 0 && blockIdx.y == 0) {
        float* ps = &ss[0][0];
        float* hs = ps + 256;
        for (int b2 = 0; b2 < BB; ++b2) {
            ps[tid] = g_zero[ZOFF_POOL + b2*CC + tid] + bp[0];
            __syncthreads();
            if (tid < 64) {
                float a = 0.f;
                for (int c = 0; c < 256; ++c) a += ps[c]*w1[c*64 + tid];
                hs[tid] = fmaxf(a, 0.f);
            }
            __syncthreads();
            float a = 0.f;
            for (int j = 0; j < 64; ++j) a += hs[j]*w2[j*256 + tid];
            g_gate[b2*CC + tid] = 1.f/(1.f + expf(-a));
            __syncthreads();
        }
    }

    if (tid < 64)
        qr[tid] = 1.f / fmaxf(sqrtf(g_zero[ZOFF_QSS + b*256 + h*64 + tid]), 1e-12f);
    #pragma unroll
    for (int v = 0; v < 4; ++v) {
        int i4 = v*256 + tid; int d = i4 >> 4, pp = (i4 & 15)*4;
        float4 kv = *(const float4*)(kbase + d*64 + pp);
        sB[d][pp]   = __float2bfloat16(kv.x + be[pp]);
        sB[d][pp+1] = __float2bfloat16(kv.y + be[pp+1]);
        sB[d][pp+2] = __float2bfloat16(kv.z + be[pp+2]);
        sB[d][pp+3] = __float2bfloat16(kv.w + be[pp+3]);
    }
    __syncthreads();
    #pragma unroll
    for (int l = 0; l < 2; ++l) {
        int i8 = l*256 + tid; int r = i8 >> 3, sg = (i8 & 7)*8;
        uint4 v = *(const uint4*)(g_qkv_bf + ((size_t)(b*NNT + n0 + r))*768 + h*64 + sg);
        const __nv_bfloat162* hh = (const __nv_bfloat162*)&v;
        __nv_bfloat16 outv[8];
        #pragma unroll
        for (int j = 0; j < 4; ++j) {
            float2 f = __bfloat1622float2(hh[j]);
            outv[j*2]   = __float2bfloat16(f.x * qr[sg + j*2]);
            outv[j*2+1] = __float2bfloat16(f.y * qr[sg + j*2+1]);
        }
        *(uint4*)&sA[r][sg] = *(uint4*)outv;
    }
    __syncthreads();
    float acc1[2][2][4] = {};
    #pragma unroll
    for (int kk = 0; kk < 64; kk += 16) {
        unsigned int af[2][4];
        #pragma unroll
        for (int mt = 0; mt < 2; ++mt)
            ldm_x4(af[mt], &sA[wm*32 + mt*16 + (lane & 15)][kk + (lane >> 4)*8]);
        unsigned int bfr[4];
        ldm_x4_t(bfr, &sB[kk + (lane & 15)][wn*16 + (lane >> 4)*8]);
        #pragma unroll
        for (int mt = 0; mt < 2; ++mt)
            #pragma unroll
            for (int nt = 0; nt < 2; ++nt)
                mma16816(acc1[mt][nt], af[mt], bfr[nt*2], bfr[nt*2+1]);
    }
    float ts = temp[h];
    #pragma unroll
    for (int mt = 0; mt < 2; ++mt) {
        int r = wm*32 + mt*16 + (lane >> 2);
        #pragma unroll
        for (int nt = 0; nt < 2; ++nt) {
            int c = wn*16 + nt*8 + (lane & 3)*2;
            ss[r][c]     = acc1[mt][nt][0]*ts;
            ss[r][c+1]   = acc1[mt][nt][1]*ts;
            ss[r+8][c]   = acc1[mt][nt][2]*ts;
            ss[r+8][c+1] = acc1[mt][nt][3]*ts;
        }
    }
    __syncthreads();
    #pragma unroll
    for (int v = 0; v < 4; ++v) {
        int i4 = v*256 + tid; int d = i4 >> 4, pp = (i4 & 15)*4;
        float4 vv = *(const float4*)(vbase + d*64 + pp);
        sA[d][pp]   = __float2bfloat16(vv.x + be[pp]);
        sA[d][pp+1] = __float2bfloat16(vv.y + be[pp+1]);
        sA[d][pp+2] = __float2bfloat16(vv.z + be[pp+2]);
        sA[d][pp+3] = __float2bfloat16(vv.w + be[pp+3]);
    }
    {
        int row = tid >> 2, g4 = (tid & 3)*16;
        float e[16];
        float mx = -1e30f;
        #pragma unroll
        for (int p = 0; p < 16; ++p) { e[p] = ss[row][g4+p]; mx = fmaxf(mx, e[p]); }
        mx = fmaxf(mx, __shfl_xor_sync(0xffffffffu, mx, 1));
        mx = fmaxf(mx, __shfl_xor_sync(0xffffffffu, mx, 2));
        float sum = 0.f;
        #pragma unroll
        for (int p = 0; p < 16; ++p) { e[p] = __expf(e[p] - mx); sum += e[p]; }
        sum += __shfl_xor_sync(0xffffffffu, sum, 1);
        sum += __shfl_xor_sync(0xffffffffu, sum, 2);
        float inv = 1.f/sum;
        #pragma unroll
        for (int p = 0; p < 16; ++p)
            sB[g4+p][row] = __float2bfloat16(e[p]*inv);
    }
    __syncthreads();
    float acc2[2][2][4] = {};
    #pragma unroll
    for (int kk = 0; kk < 64; kk += 16) {
        unsigned int af[2][4];
        #pragma unroll
        for (int mt = 0; mt < 2; ++mt)
            ldm_x4(af[mt], &sA[wm*32 + mt*16 + (lane & 15)][kk + (lane >> 4)*8]);
        unsigned int bfr[4];
        ldm_x4_t(bfr, &sB[kk + (lane & 15)][wn*16 + (lane >> 4)*8]);
        #pragma unroll
        for (int mt = 0; mt < 2; ++mt)
            #pragma unroll
            for (int nt = 0; nt < 2; ++nt)
                mma16816(acc2[mt][nt], af[mt], bfr[nt*2], bfr[nt*2+1]);
    }
    __nv_bfloat16* sabase = g_sa_bf + (size_t)b*NNT*CC;
    #pragma unroll
    for (int mt = 0; mt < 2; ++mt) {
        int d0 = wm*32 + mt*16 + (lane >> 2);
        #pragma unroll
        for (int nt = 0; nt < 2; ++nt) {
            int nc = n0 + wn*16 + nt*8 + (lane & 3)*2;
            *(__nv_bfloat162*)&sabase[(size_t)(d0*4 + h)*NNT + nc] =
                __floats2bfloat162_rn(acc2[mt][nt][0], acc2[mt][nt][1]);
            *(__nv_bfloat162*)&sabase[(size_t)((d0+8)*4 + h)*NNT + nc] =
                __floats2bfloat162_rn(acc2[mt][nt][2], acc2[mt][nt][3]);
        }
    }
}

// ---------------- launch ----------------
extern "C" void kernel_launch(void* const* d_in, const int* in_sizes, int n_in,
                              void* d_out, int out_size)
{
    const float* x      = (const float*)d_in[0];
    const float* pos    = (const float*)d_in[1];
    const float* ln_g   = (const float*)d_in[2];
    const float* ln_b   = (const float*)d_in[3];
    const float* gamma  = (const float*)d_in[4];
    const float* temp2  = (const float*)d_in[5];
    const float* w_qkv  = (const float*)d_in[6];
    const float* w_e    = (const float*)d_in[7];
    const float* b_e    = (const float*)d_in[8];
    const float* w_pool = (const float*)d_in[9];
    const float* b_pool = (const float*)d_in[10];
    const float* w_fc1  = (const float*)d_in[11];
    const float* w_fc2  = (const float*)d_in[12];
    const float* b_out1 = (const float*)d_in[14];
    const float* b_out2 = (const float*)d_in[16];
    const float* w_c1   = (const float*)d_in[17];
    const float* b_c1   = (const float*)d_in[18];
    const float* w_c2   = (const float*)d_in[19];
    const float* b_c2   = (const float*)d_in[20];

    __nv_bfloat16 *p_h1b, *p_c2b, *p_xtbf, *p_xctbf, *p_sabf;
    __nv_bfloat16 *p_wq, *p_w1, *p_w2, *p_qkvbf;
    float *p_gate, *p_zero;
    cudaGetSymbolAddress((void**)&p_h1b,   g_h1b);
    cudaGetSymbolAddress((void**)&p_c2b,   g_c2b);
    cudaGetSymbolAddress((void**)&p_xtbf,  g_xt_bf);
    cudaGetSymbolAddress((void**)&p_xctbf, g_xct_bf);
    cudaGetSymbolAddress((void**)&p_qkvbf, g_qkv_bf);
    cudaGetSymbolAddress((void**)&p_sabf,  g_sa_bf);
    cudaGetSymbolAddress((void**)&p_wq,    g_wqkv_bf);
    cudaGetSymbolAddress((void**)&p_w1,    g_wo1_bf);
    cudaGetSymbolAddress((void**)&p_w2,    g_wo2_bf);
    cudaGetSymbolAddress((void**)&p_gate,  g_gate);
    cudaGetSymbolAddress((void**)&p_zero,  g_zero);

    static int s_attr_done = 0;
    if (!s_attr_done) {
        cudaFuncSetAttribute(k_megaln,
            cudaFuncAttributeMaxDynamicSharedMemorySize, 55296);
        cudaFuncSetAttribute(k_mma,
            cudaFuncAttributeMaxDynamicSharedMemorySize, 71680);
        s_attr_done = 1;
    }

    k_init <<<3456, 256>>>(w_qkv, (const float*)d_in[13],
                           (const float*)d_in[15], w_e);
    // MHCResBlock: grouped convs via HMMA with fused stats
    k_convmma<<<dim3(27,16), 256>>>(x, (const __nv_bfloat16*)0, w_c1, b_c1, p_h1b,
                                    (const float*)0, (const float*)0,
                                    p_zero + ZOFF_CS1S, p_zero + ZOFF_CS1Q);
    k_convmma<<<dim3(27,16), 256>>>((const float*)0, p_h1b, w_c2, b_c2, p_c2b,
                                    p_zero + ZOFF_CS1S, p_zero + ZOFF_CS1Q,
                                    p_zero + ZOFF_CS2S, p_zero + ZOFF_CS2Q);
    // mega-fused transpose + xc + double-LN + pool + d_out(x_n)
    k_megaln<<<dim3(432, BB), 256, 55296>>>(x, pos, ln_g, ln_b, w_pool,
                                            (float*)d_out);
    // qkv (pipelined bf16 HMMA, fused q sum-squares + fused K/V low-rank proj)
    k_mma  <<<dim3(6,216,1), 256, 71680>>>(p_xtbf, (const __nv_bfloat16*)0, p_wq,
                                    (const __nv_bfloat16*)0, (const float*)0,
                                    (const float*)0, (const float*)0,
                                    p_qkvbf, 768, 768, 1,
                                    (float*)0, (const float*)0);
    // spatial attention (+ fused CA gate in block 0)
    k_attn <<<dim3(216, BB*NHH), 256>>>(b_e, temp2, b_pool, w_fc1, w_fc2);
    // both output projections with fused gamma-residual into d_out
    k_mma  <<<dim3(1,216,2), 256, 71680>>>(p_sabf, p_xctbf, p_w1, p_w2,
                                    b_out1, b_out2, p_gate,
                                    (__nv_bfloat16*)0, 128, 256, 0,
                                    (float*)d_out, gamma);
}

// round 16
// speedup vs baseline: 1.0194x; 1.0022x over previous
#include <cuda_runtime.h>
#include <cuda_bf16.h>
#include <cstdint>
#include <math.h>

#define BB 2
#define CC 256
#define NNT 13824
#define NHH 4
#define MTOT (BB*NNT)

// ---------------- scratch ----------------
__device__ __nv_bfloat16 g_h1b[BB*CC*NNT];
__device__ __nv_bfloat16 g_c2b[BB*CC*NNT];
__device__ __nv_bfloat16 g_xt_bf [BB*NNT*CC];
__device__ __nv_bfloat16 g_xct_bf[BB*NNT*CC];
__device__ __nv_bfloat16 g_qkv_bf[(size_t)BB*NNT*768];
__device__ __nv_bfloat16 g_sa_bf [BB*NNT*CC];
__device__ __nv_bfloat16 g_wqkv_bf[256*768];
__device__ __nv_bfloat16 g_wo1_bf [256*128];
__device__ __nv_bfloat16 g_wo2_bf [256*128];
__device__ __nv_bfloat16 g_we_bf  [NNT*64];
#define ZOFF_POOL 0
#define ZOFF_QSS  512
#define ZOFF_CS1S 1024
#define ZOFF_CS1Q 1536
#define ZOFF_CS2S 2048
#define ZOFF_CS2Q 2560
#define ZOFF_KP   3072
#define ZOFF_VP   35840
#define ZTOT      68608
__device__ float g_zero[ZTOT];
__device__ float g_gate[BB*CC];

// ---------------- asm helpers ----------------
__device__ __forceinline__ void ldm_x4(unsigned int (&r)[4], const void* p) {
    unsigned int a = (unsigned int)__cvta_generic_to_shared(p);
    asm volatile("ldmatrix.sync.aligned.m8n8.x4.shared.b16 {%0,%1,%2,%3}, [%4];"
        : "=r"(r[0]),"=r"(r[1]),"=r"(r[2]),"=r"(r[3]) : "r"(a));
}
__device__ __forceinline__ void ldm_x4_t(unsigned int (&r)[4], const void* p) {
    unsigned int a = (unsigned int)__cvta_generic_to_shared(p);
    asm volatile("ldmatrix.sync.aligned.m8n8.x4.trans.shared.b16 {%0,%1,%2,%3}, [%4];"
        : "=r"(r[0]),"=r"(r[1]),"=r"(r[2]),"=r"(r[3]) : "r"(a));
}
__device__ __forceinline__ void mma16816(float (&d)[4], const unsigned int (&a)[4],
                                         unsigned int b0, unsigned int b1) {
    asm volatile("mma.sync.aligned.m16n8k16.row.col.f32.bf16.bf16.f32 "
        "{%0,%1,%2,%3},{%4,%5,%6,%7},{%8,%9},{%0,%1,%2,%3};"
        : "+f"(d[0]),"+f"(d[1]),"+f"(d[2]),"+f"(d[3])
        : "r"(a[0]),"r"(a[1]),"r"(a[2]),"r"(a[3]),"r"(b0),"r"(b1));
}
__device__ __forceinline__ void cpa16(void* dst, const void* src) {
    unsigned int d = (unsigned int)__cvta_generic_to_shared(dst);
    asm volatile("cp.async.cg.shared.global [%0], [%1], 16;" :: "r"(d), "l"(src));
}
__device__ __forceinline__ void cp_commit() { asm volatile("cp.async.commit_group;"); }
template<int N> __device__ __forceinline__ void cp_wait() {
    asm volatile("cp.async.wait_group %0;" :: "n"(N));
}

// ---------------- kernels ----------------
__global__ void k_init(const float* __restrict__ wq, const float* __restrict__ w1,
                       const float* __restrict__ w2, const float* __restrict__ we)
{
    int i = blockIdx.x*256 + threadIdx.x;
    if (i < ZTOT) g_zero[i] = 0.f;
    if (i < 196608) g_wqkv_bf[i] = __float2bfloat16(wq[i]);
    if (i < 32768)  { g_wo1_bf[i] = __float2bfloat16(w1[i]);
                      g_wo2_bf[i] = __float2bfloat16(w2[i]); }
    if (i < NNT*64) g_we_bf[i] = __float2bfloat16(we[i]);
}

// grouped 1x1x1 conv via HMMA; conv2 input streamed (read-once).
__global__ __launch_bounds__(256) void k_convmma(
    const float* __restrict__ srcf, const __nv_bfloat16* __restrict__ srcb,
    const float* __restrict__ w, const float* __restrict__ bias,
    __nv_bfloat16* __restrict__ dst,
    const float* __restrict__ sin_s, const float* __restrict__ sin_q,
    float* __restrict__ sout_s, float* __restrict__ sout_q)
{
    __shared__ __align__(16) __nv_bfloat16 Ws[32][40];
    __shared__ __align__(16) __nv_bfloat16 Bs[32][520];
    __shared__ float sm[32], sr[32], bss[32];
    __shared__ float sst[8][32][2];
    int bg = blockIdx.y; int b = bg >> 3; int g = bg & 7;
    int n0 = blockIdx.x*512;
    int tid = threadIdx.x, lane = tid & 31, wid = tid >> 5;
    int cbase = b*CC + g*32;

    #pragma unroll
    for (int p = 0; p < 4; ++p) {
        int idx = p*256 + tid;
        Ws[idx & 31][idx >> 5] = __float2bfloat16(w[g*1024 + idx]);
    }
    if (tid < 32) {
        bss[tid] = bias[g*32 + tid];
        if (srcb) {
            float s = sin_s[cbase+tid], q = sin_q[cbase+tid];
            float m = s*(1.f/NNT);
            sm[tid] = m;
            sr[tid] = rsqrtf(q*(1.f/NNT) - m*m + 1e-5f);
        }
    }
    __syncthreads();

    if (srcf) {
        #pragma unroll
        for (int p = 0; p < 16; ++p) {
            int idx = p*256 + tid;
            int row = idx >> 7, cq = idx & 127;
            float4 v = *(const float4*)(srcf + (size_t)(cbase+row)*NNT + n0 + cq*4);
            *(__nv_bfloat162*)&Bs[row][cq*4]   = __floats2bfloat162_rn(v.x, v.y);
            *(__nv_bfloat162*)&Bs[row][cq*4+2] = __floats2bfloat162_rn(v.z, v.w);
        }
    } else {
        #pragma unroll
        for (int p = 0; p < 8; ++p) {
            int idx = p*256 + tid;
            int row = idx >> 6, sg = idx & 63;
            uint4 v = __ldcs((const uint4*)(srcb + (size_t)(cbase+row)*NNT + n0 + sg*8));
            const __nv_bfloat162* hh = (const __nv_bfloat162*)&v;
            float m = sm[row], r = sr[row];
            __nv_bfloat16 o[8];
            #pragma unroll
            for (int j = 0; j < 4; ++j) {
                float2 f = __bfloat1622float2(hh[j]);
                float fx = (f.x - m)*r; fx = fx >= 0.f ? fx : 0.01f*fx;
                float fy = (f.y - m)*r; fy = fy >= 0.f ? fy : 0.01f*fy;
                *(__nv_bfloat162*)&o[j*2] = __floats2bfloat162_rn(fx, fy);
            }
            *(uint4*)&Bs[row][sg*8] = *(uint4*)o;
        }
    }
    __syncthreads();

    float acc[2][8][4] = {};
    #pragma unroll
    for (int kk = 0; kk < 2; ++kk) {
        unsigned int af[2][4];
        #pragma unroll
        for (int mt = 0; mt < 2; ++mt)
            ldm_x4(af[mt], &Ws[mt*16 + (lane & 15)][kk*16 + (lane >> 4)*8]);
        unsigned int bfr[4][4];
        #pragma unroll
        for (int ng = 0; ng < 4; ++ng)
            ldm_x4_t(bfr[ng], &Bs[kk*16 + (lane & 15)][wid*64 + ng*16 + (lane >> 4)*8]);
        #pragma unroll
        for (int mt = 0; mt < 2; ++mt)
            #pragma unroll
            for (int nt = 0; nt < 8; ++nt)
                mma16816(acc[mt][nt], af[mt],
                         bfr[nt>>1][(nt&1)*2], bfr[nt>>1][(nt&1)*2+1]);
    }

    float ssum[2][2] = {}, ssq[2][2] = {};
    #pragma unroll
    for (int mt = 0; mt < 2; ++mt) {
        #pragma unroll
        for (int h = 0; h < 2; ++h) {
            int oc = mt*16 + (lane >> 2) + h*8;
            float bv = bss[oc];
            __nv_bfloat16* drow = dst + (size_t)(cbase+oc)*NNT + n0 + wid*64;
            #pragma unroll
            for (int nt = 0; nt < 8; ++nt) {
                float v0 = acc[mt][nt][h*2+0] + bv;
                float v1 = acc[mt][nt][h*2+1] + bv;
                *(__nv_bfloat162*)&drow[nt*8 + (lane & 3)*2] =
                    __floats2bfloat162_rn(v0, v1);
                ssum[mt][h] += v0 + v1;
                ssq [mt][h] += v0*v0 + v1*v1;
            }
        }
    }
    #pragma unroll
    for (int mt = 0; mt < 2; ++mt)
        #pragma unroll
        for (int h = 0; h < 2; ++h) {
            float s = ssum[mt][h], q = ssq[mt][h];
            s += __shfl_xor_sync(0xffffffffu, s, 1);
            q += __shfl_xor_sync(0xffffffffu, q, 1);
            s += __shfl_xor_sync(0xffffffffu, s, 2);
            q += __shfl_xor_sync(0xffffffffu, q, 2);
            if ((lane & 3) == 0) {
                int oc = mt*16 + (lane >> 2) + h*8;
                sst[wid][oc][0] = s;
                sst[wid][oc][1] = q;
            }
        }
    __syncthreads();
    if (tid < 64) {
        int oc = tid & 31, which = tid >> 5;
        float s = 0.f;
        #pragma unroll
        for (int ww = 0; ww < 8; ++ww) s += sst[ww][oc][which];
        atomicAdd(&(which ? sout_q : sout_s)[cbase+oc], s);
    }
}

// mega-fused LN kernel; streaming hints on read-once c2b and write-once d_out.
__global__ __launch_bounds__(256) void k_megaln(
    const float* __restrict__ x, const float* __restrict__ pos,
    const float* __restrict__ lg, const float* __restrict__ lb,
    const float* __restrict__ wp, float* __restrict__ dout)
{
    extern __shared__ float dsm[];
    float*  xs  = dsm;
    float2* st2 = (float2*)(dsm + 8448);
    float2* lgb = (float2*)(dsm + 8960);
    __nv_bfloat16* cs = (__nv_bfloat16*)(dsm + 9472);
    int tid = threadIdx.x, tx = tid & 31, ty = tid >> 5;
    int lane = tid & 31, w = tid >> 5;
    int n0 = blockIdx.x*32, b = blockIdx.y;
    {
        float s = g_zero[ZOFF_CS2S + b*256 + tid];
        float q = g_zero[ZOFF_CS2Q + b*256 + tid];
        float m = s*(1.f/NNT);
        st2[tid] = make_float2(m, rsqrtf(q*(1.f/NNT) - m*m + 1e-5f));
        lgb[tid] = make_float2(lg[tid], lb[tid]);
    }
    __syncthreads();
    for (int cc = ty; cc < 256; cc += 8) {
        size_t s = (size_t)(b*CC + cc)*NNT + n0 + tx;
        float xv = x[s];
        float2 st = st2[cc];
        float cv = __bfloat162float(__ldcs(&g_c2b[s]));
        float hv = (cv - st.x)*st.y + xv;
        xs[cc*33 + tx] = xv;
        cs[cc*34 + tx] = __float2bfloat16(hv >= 0.f ? hv : 0.01f*hv);
    }
    __syncthreads();
    float pacc[8];
    #pragma unroll
    for (int j = 0; j < 8; ++j) pacc[j] = 0.f;
    for (int t8 = 0; t8 < 4; ++t8) {
        int tok = w + t8*8;
        const float* prow = pos + (size_t)(n0 + tok)*CC;
        float v1[8], v2[8];
        float s1 = 0.f, q1 = 0.f, s2 = 0.f, q2 = 0.f;
        #pragma unroll
        for (int q = 0; q < 4; ++q) {
            int c0 = lane*2 + q*64;
            float2 p2 = *(const float2*)(prow + c0);
            float ax = xs[c0*33 + tok] + p2.x;
            float ay = xs[(c0+1)*33 + tok] + p2.y;
            float dx = __bfloat162float(cs[c0*34 + tok]) + p2.x;
            float dy = __bfloat162float(cs[(c0+1)*34 + tok]) + p2.y;
            v1[q*2] = ax; v1[q*2+1] = ay;
            v2[q*2] = dx; v2[q*2+1] = dy;
            s1 += ax + ay; q1 += ax*ax + ay*ay;
            s2 += dx + dy; q2 += dx*dx + dy*dy;
        }
        #pragma unroll
        for (int o = 16; o; o >>= 1) {
            s1 += __shfl_xor_sync(0xffffffffu, s1, o);
            q1 += __shfl_xor_sync(0xffffffffu, q1, o);
            s2 += __shfl_xor_sync(0xffffffffu, s2, o);
            q2 += __shfl_xor_sync(0xffffffffu, q2, o);
        }
        float m1 = s1*(1.f/CC), r1 = rsqrtf(q1*(1.f/CC) - m1*m1 + 1e-5f);
        float m2 = s2*(1.f/CC), r2 = rsqrtf(q2*(1.f/CC) - m2*m2 + 1e-5f);
        float wpt = wp[n0 + tok];
        size_t gbase = ((size_t)b*NNT + n0 + tok)*CC;
        #pragma unroll
        for (int q = 0; q < 4; ++q) {
            int c0 = lane*2 + q*64;
            float4 gb = *(const float4*)(lgb + c0);
            float o1x = (v1[q*2]   - m1)*r1*gb.x + gb.y;
            float o1y = (v1[q*2+1] - m1)*r1*gb.z + gb.w;
            float o2x = (v2[q*2]   - m2)*r2*gb.x + gb.y;
            float o2y = (v2[q*2+1] - m2)*r2*gb.z + gb.w;
            *(__nv_bfloat162*)&g_xt_bf [gbase + c0] = __floats2bfloat162_rn(o1x, o1y);
            *(__nv_bfloat162*)&g_xct_bf[gbase + c0] = __floats2bfloat162_rn(o2x, o2y);
            xs[c0*33 + tok]     = o1x;
            xs[(c0+1)*33 + tok] = o1y;
            pacc[q*2]   += o2x*wpt;
            pacc[q*2+1] += o2y*wpt;
        }
    }
    __syncthreads();
    float* pws = (float*)cs;
    #pragma unroll
    for (int q = 0; q < 4; ++q) {
        int c0 = lane*2 + q*64;
        *(float2*)&pws[w*256 + c0] = make_float2(pacc[q*2], pacc[q*2+1]);
    }
    __syncthreads();
    {
        float s = 0.f;
        #pragma unroll
        for (int ww = 0; ww < 8; ++ww) s += pws[ww*256 + tid];
        atomicAdd(&g_zero[ZOFF_POOL + b*256 + tid], s);
    }
    for (int cc = ty; cc < 256; cc += 8)
        __stcs(&dout[(size_t)(b*CC + cc)*NNT + n0 + tx], xs[cc*33 + tx]);
}

// bf16 HMMA GEMM, K=64 chunks, cp.async double buffering, dynamic smem.
#define AS_(st,r,c) smem_mma[(size_t)(st)*9216 + (r)*72 + (c)]
#define BS_(st,r,c) smem_mma[18432 + (size_t)(st)*8704 + (r)*136 + (c)]
__global__ __launch_bounds__(256) void k_mma(
    const __nv_bfloat16* __restrict__ A, const __nv_bfloat16* __restrict__ A2,
    const __nv_bfloat16* __restrict__ Bw, const __nv_bfloat16* __restrict__ Bw2,
    const float* __restrict__ bias, const float* __restrict__ bias2,
    const float* __restrict__ gate,
    __nv_bfloat16* __restrict__ Cb, int Nld, int ldc, int doqss,
    float* __restrict__ dout, const float* __restrict__ gfin)
{
    extern __shared__ __nv_bfloat16 smem_mma[];
    int tid = threadIdx.x;
    int wid = tid >> 5, lane = tid & 31;
    int wm = wid >> 2;
    int wn = wid & 3;
    int m0 = blockIdx.y * 128;
    int n0 = blockIdx.x * 128;
    int coff = 0;
    const float* grow = nullptr;
    if (blockIdx.z == 1) {
        A = A2; Bw = Bw2; bias = bias2; coff = 128;
        grow = gate + (m0 / NNT)*CC;
    }

    float acc[4][4][4] = {};

    #pragma unroll
    for (int p = 0; p < 4; ++p) {
        int idx = p*256 + tid; int r = idx >> 3, sg = idx & 7;
        cpa16(&AS_(0, r, sg*8), A + (size_t)(m0 + r)*256 + sg*8);
    }
    #pragma unroll
    for (int p = 0; p < 4; ++p) {
        int idx = p*256 + tid; int r = idx >> 4, sg = idx & 15;
        cpa16(&BS_(0, r, sg*8), Bw + (size_t)r*Nld + n0 + sg*8);
    }
    cp_commit();

    for (int it = 0; it < 4; ++it) {
        int k0 = it*64, st = it & 1;
        if (it < 3) {
            int kn = k0 + 64, sn = st ^ 1;
            #pragma unroll
            for (int p = 0; p < 4; ++p) {
                int idx = p*256 + tid; int r = idx >> 3, sg = idx & 7;
                cpa16(&AS_(sn, r, sg*8), A + (size_t)(m0 + r)*256 + kn + sg*8);
            }
            #pragma unroll
            for (int p = 0; p < 4; ++p) {
                int idx = p*256 + tid; int r = idx >> 4, sg = idx & 15;
                cpa16(&BS_(sn, r, sg*8), Bw + (size_t)(kn + r)*Nld + n0 + sg*8);
            }
            cp_commit();
            cp_wait<1>();
        } else {
            cp_wait<0>();
        }
        __syncthreads();
        if (grow) {
            #pragma unroll
            for (int p = 0; p < 4; ++p) {
                int idx = p*256 + tid; int r = idx >> 3, sg = idx & 7;
                __nv_bfloat16* qp = &AS_(st, r, sg*8);
                #pragma unroll
                for (int j = 0; j < 8; ++j)
                    qp[j] = __float2bfloat16(__bfloat162float(qp[j])*grow[k0+sg*8+j]);
            }
            __syncthreads();
        }
        #pragma unroll
        for (int kk = 0; kk < 4; ++kk) {
            unsigned int af[4][4];
            #pragma unroll
            for (int mt = 0; mt < 4; ++mt)
                ldm_x4(af[mt], &AS_(st, wm*64 + mt*16 + (lane & 15), kk*16 + (lane >> 4)*8));
            unsigned int bfr[2][4];
            #pragma unroll
            for (int g2 = 0; g2 < 2; ++g2)
                ldm_x4_t(bfr[g2], &BS_(st, kk*16 + (lane & 15), wn*32 + g2*16 + (lane >> 4)*8));
            #pragma unroll
            for (int mt = 0; mt < 4; ++mt)
                #pragma unroll
                for (int nt = 0; nt < 4; ++nt)
                    mma16816(acc[mt][nt], af[mt],
                             bfr[nt>>1][(nt&1)*2], bfr[nt>>1][(nt&1)*2+1]);
        }
        __syncthreads();
    }
    if (doqss && n0 < 256) {
        int b = m0 / NNT;
        #pragma unroll
        for (int nt = 0; nt < 4; ++nt) {
            float s0 = 0.f, s1 = 0.f;
            #pragma unroll
            for (int mt = 0; mt < 4; ++mt) {
                #pragma unroll
                for (int h = 0; h < 2; ++h) {
                    float a0 = acc[mt][nt][h*2+0], a1 = acc[mt][nt][h*2+1];
                    s0 += a0*a0; s1 += a1*a1;
                }
            }
            #pragma unroll
            for (int o = 4; o <= 16; o <<= 1) {
                s0 += __shfl_xor_sync(0xffffffffu, s0, o);
                s1 += __shfl_xor_sync(0xffffffffu, s1, o);
            }
            if ((lane >> 2) == 0) {
                int col = n0 + wn*32 + nt*8 + (lane & 3)*2;
                atomicAdd(&g_zero[ZOFF_QSS + b*256 + col],   s0);
                atomicAdd(&g_zero[ZOFF_QSS + b*256 + col+1], s1);
            }
        }
    }
    if (doqss && n0 >= 256) {
        __nv_bfloat16* Cs = smem_mma;
        __nv_bfloat16* Es = smem_mma + 17408;
        int b = m0 / NNT;
        int n0t = m0 % NNT;
        int which = (n0 >= 512) ? 1 : 0;
        int dbase = n0 - 256 - which*256;
        #pragma unroll
        for (int mt = 0; mt < 4; ++mt) {
            int row0 = wm*64 + mt*16 + (lane >> 2);
            #pragma unroll
            for (int nt = 0; nt < 4; ++nt) {
                int col = wn*32 + nt*8 + (lane & 3)*2;
                #pragma unroll
                for (int h = 0; h < 2; ++h)
                    *(__nv_bfloat162*)&Cs[(row0 + h*8)*136 + col] =
                        __floats2bfloat162_rn(acc[mt][nt][h*2+0], acc[mt][nt][h*2+1]);
            }
        }
        #pragma unroll
        for (int p = 0; p < 4; ++p) {
            int idx = p*256 + tid; int r = idx >> 3, sg = idx & 7;
            *(uint4*)&Es[r*72 + sg*8] =
                *(const uint4*)(g_we_bf + (size_t)(n0t + r)*64 + sg*8);
        }
        __syncthreads();
        float a2[8][4] = {};
        #pragma unroll
        for (int kk = 0; kk < 128; kk += 16) {
            unsigned int af[4];
            ldm_x4_t(af, &Cs[(kk + (lane & 7) + ((lane >> 4) << 3))*136
                             + wid*16 + ((lane >> 3) & 1)*8]);
            unsigned int bfr[4][4];
            #pragma unroll
            for (int ng = 0; ng < 4; ++ng)
                ldm_x4_t(bfr[ng], &Es[(kk + (lane & 15))*72 + ng*16 + (lane >> 4)*8]);
            #pragma unroll
            for (int nt = 0; nt < 8; ++nt)
                mma16816(a2[nt], af, bfr[nt>>1][(nt&1)*2], bfr[nt>>1][(nt&1)*2+1]);
        }
        float* out = &g_zero[ZOFF_KP + which*32768 + b*16384];
        int m = dbase + wid*16 + (lane >> 2);
        #pragma unroll
        for (int nt = 0; nt < 8; ++nt) {
            int p = nt*8 + (lane & 3)*2;
            atomicAdd(&out[m*64 + p],       a2[nt][0]);
            atomicAdd(&out[m*64 + p + 1],   a2[nt][1]);
            atomicAdd(&out[(m+8)*64 + p],   a2[nt][2]);
            atomicAdd(&out[(m+8)*64 + p+1], a2[nt][3]);
        }
        return;
    }
    if (gfin) {
        float* ts = (float*)smem_mma;
        const int TS = 132;
        int b = m0 / NNT;
        int n0t = m0 % NNT;
        #pragma unroll
        for (int nt = 0; nt < 4; ++nt) {
            int ll = wn*32 + nt*8 + (lane & 3)*2;
            float gm0 = gfin[coff + ll], gm1 = gfin[coff + ll + 1];
            float b0 = bias[ll], b1 = bias[ll + 1];
            #pragma unroll
            for (int mt = 0; mt < 4; ++mt) {
                #pragma unroll
                for (int h = 0; h < 2; ++h) {
                    int rr = wm*64 + mt*16 + (lane >> 2) + h*8;
                    ts[ll*TS + rr]     = (acc[mt][nt][h*2+0] + b0)*gm0;
                    ts[(ll+1)*TS + rr] = (acc[mt][nt][h*2+1] + b1)*gm1;
                }
            }
        }
        __syncthreads();
        #pragma unroll
        for (int r = 0; r < 16; ++r) {
            int c = wid*16 + r;
            float* dp = dout + (size_t)(b*CC + coff + c)*NNT + n0t;
            float4 dv = __ldcs((const float4*)(dp + lane*4));
            dv.x += ts[c*TS + lane*4 + 0];
            dv.y += ts[c*TS + lane*4 + 1];
            dv.z += ts[c*TS + lane*4 + 2];
            dv.w += ts[c*TS + lane*4 + 3];
            __stcs((float4*)(dp + lane*4), dv);
        }
        return;
    }
    #pragma unroll
    for (int mt = 0; mt < 4; ++mt) {
        int row0 = m0 + wm*64 + mt*16 + (lane >> 2);
        #pragma unroll
        for (int nt = 0; nt < 4; ++nt) {
            int col = wn*32 + nt*8 + (lane & 3)*2;
            #pragma unroll
            for (int h = 0; h < 2; ++h) {
                int r = row0 + h*8;
                float v0 = acc[mt][nt][h*2+0];
                float v1 = acc[mt][nt][h*2+1];
                if (bias) { v0 += bias[n0+col]; v1 += bias[n0+col+1]; }
                __nv_bfloat16* p = Cb + (size_t)r*ldc + coff + n0 + col;
                p[0] = __float2bfloat16(v0); p[1] = __float2bfloat16(v1);
            }
        }
    }
}

// fused attention tile; q reads streamed (read-once); block (0,0) does CA gate.
__global__ __launch_bounds__(256) void k_attn(
    const float* __restrict__ be, const float* __restrict__ temp,
    const float* __restrict__ bp, const float* __restrict__ w1,
    const float* __restrict__ w2)
{
    int bh = blockIdx.y; int b = bh >> 2, h = bh & 3;
    int n0 = blockIdx.x*64;
    __shared__ __align__(16) __nv_bfloat16 sA[64][72];
    __shared__ __align__(16) __nv_bfloat16 sB[64][72];
    __shared__ float ss[64][68];
    __shared__ float qr[64];
    int tid = threadIdx.x;
    int wid = tid >> 5, lane = tid & 31;
    int wm = wid & 1, wn = wid >> 1;
    const float* kbase = &g_zero[ZOFF_KP + bh*4096];
    const float* vbase = &g_zero[ZOFF_VP + bh*4096];

    if (blockIdx.x == 0 && blockIdx.y == 0) {
        float* ps = &ss[0][0];
        float* hs = ps + 256;
        for (int b2 = 0; b2 < BB; ++b2) {
            ps[tid] = g_zero[ZOFF_POOL + b2*CC + tid] + bp[0];
            __syncthreads();
            if (tid < 64) {
                float a = 0.f;
                for (int c = 0; c < 256; ++c) a += ps[c]*w1[c*64 + tid];
                hs[tid] = fmaxf(a, 0.f);
            }
            __syncthreads();
            float a = 0.f;
            for (int j = 0; j < 64; ++j) a += hs[j]*w2[j*256 + tid];
            g_gate[b2*CC + tid] = 1.f/(1.f + expf(-a));
            __syncthreads();
        }
    }

    if (tid < 64)
        qr[tid] = 1.f / fmaxf(sqrtf(g_zero[ZOFF_QSS + b*256 + h*64 + tid]), 1e-12f);
    #pragma unroll
    for (int v = 0; v < 4; ++v) {
        int i4 = v*256 + tid; int d = i4 >> 4, pp = (i4 & 15)*4;
        float4 kv = *(const float4*)(kbase + d*64 + pp);
        sB[d][pp]   = __float2bfloat16(kv.x + be[pp]);
        sB[d][pp+1] = __float2bfloat16(kv.y + be[pp+1]);
        sB[d][pp+2] = __float2bfloat16(kv.z + be[pp+2]);
        sB[d][pp+3] = __float2bfloat16(kv.w + be[pp+3]);
    }
    __syncthreads();
    #pragma unroll
    for (int l = 0; l < 2; ++l) {
        int i8 = l*256 + tid; int r = i8 >> 3, sg = (i8 & 7)*8;
        uint4 v = __ldcs((const uint4*)(g_qkv_bf
                    + ((size_t)(b*NNT + n0 + r))*768 + h*64 + sg));
        const __nv_bfloat162* hh = (const __nv_bfloat162*)&v;
        __nv_bfloat16 outv[8];
        #pragma unroll
        for (int j = 0; j < 4; ++j) {
            float2 f = __bfloat1622float2(hh[j]);
            outv[j*2]   = __float2bfloat16(f.x * qr[sg + j*2]);
            outv[j*2+1] = __float2bfloat16(f.y * qr[sg + j*2+1]);
        }
        *(uint4*)&sA[r][sg] = *(uint4*)outv;
    }
    __syncthreads();
    float acc1[2][2][4] = {};
    #pragma unroll
    for (int kk = 0; kk < 64; kk += 16) {
        unsigned int af[2][4];
        #pragma unroll
        for (int mt = 0; mt < 2; ++mt)
            ldm_x4(af[mt], &sA[wm*32 + mt*16 + (lane & 15)][kk + (lane >> 4)*8]);
        unsigned int bfr[4];
        ldm_x4_t(bfr, &sB[kk + (lane & 15)][wn*16 + (lane >> 4)*8]);
        #pragma unroll
        for (int mt = 0; mt < 2; ++mt)
            #pragma unroll
            for (int nt = 0; nt < 2; ++nt)
                mma16816(acc1[mt][nt], af[mt], bfr[nt*2], bfr[nt*2+1]);
    }
    float ts = temp[h];
    #pragma unroll
    for (int mt = 0; mt < 2; ++mt) {
        int r = wm*32 + mt*16 + (lane >> 2);
        #pragma unroll
        for (int nt = 0; nt < 2; ++nt) {
            int c = wn*16 + nt*8 + (lane & 3)*2;
            ss[r][c]     = acc1[mt][nt][0]*ts;
            ss[r][c+1]   = acc1[mt][nt][1]*ts;
            ss[r+8][c]   = acc1[mt][nt][2]*ts;
            ss[r+8][c+1] = acc1[mt][nt][3]*ts;
        }
    }
    __syncthreads();
    #pragma unroll
    for (int v = 0; v < 4; ++v) {
        int i4 = v*256 + tid; int d = i4 >> 4, pp = (i4 & 15)*4;
        float4 vv = *(const float4*)(vbase + d*64 + pp);
        sA[d][pp]   = __float2bfloat16(vv.x + be[pp]);
        sA[d][pp+1] = __float2bfloat16(vv.y + be[pp+1]);
        sA[d][pp+2] = __float2bfloat16(vv.z + be[pp+2]);
        sA[d][pp+3] = __float2bfloat16(vv.w + be[pp+3]);
    }
    {
        int row = tid >> 2, g4 = (tid & 3)*16;
        float e[16];
        float mx = -1e30f;
        #pragma unroll
        for (int p = 0; p < 16; ++p) { e[p] = ss[row][g4+p]; mx = fmaxf(mx, e[p]); }
        mx = fmaxf(mx, __shfl_xor_sync(0xffffffffu, mx, 1));
        mx = fmaxf(mx, __shfl_xor_sync(0xffffffffu, mx, 2));
        float sum = 0.f;
        #pragma unroll
        for (int p = 0; p < 16; ++p) { e[p] = __expf(e[p] - mx); sum += e[p]; }
        sum += __shfl_xor_sync(0xffffffffu, sum, 1);
        sum += __shfl_xor_sync(0xffffffffu, sum, 2);
        float inv = 1.f/sum;
        #pragma unroll
        for (int p = 0; p < 16; ++p)
            sB[g4+p][row] = __float2bfloat16(e[p]*inv);
    }
    __syncthreads();
    float acc2[2][2][4] = {};
    #pragma unroll
    for (int kk = 0; kk < 64; kk += 16) {
        unsigned int af[2][4];
        #pragma unroll
        for (int mt = 0; mt < 2; ++mt)
            ldm_x4(af[mt], &sA[wm*32 + mt*16 + (lane & 15)][kk + (lane >> 4)*8]);
        unsigned int bfr[4];
        ldm_x4_t(bfr, &sB[kk + (lane & 15)][wn*16 + (lane >> 4)*8]);
        #pragma unroll
        for (int mt = 0; mt < 2; ++mt)
            #pragma unroll
            for (int nt = 0; nt < 2; ++nt)
                mma16816(acc2[mt][nt], af[mt], bfr[nt*2], bfr[nt*2+1]);
    }
    __nv_bfloat16* sabase = g_sa_bf + (size_t)b*NNT*CC;
    #pragma unroll
    for (int mt = 0; mt < 2; ++mt) {
        int d0 = wm*32 + mt*16 + (lane >> 2);
        #pragma unroll
        for (int nt = 0; nt < 2; ++nt) {
            int nc = n0 + wn*16 + nt*8 + (lane & 3)*2;
            *(__nv_bfloat162*)&sabase[(size_t)(d0*4 + h)*NNT + nc] =
                __floats2bfloat162_rn(acc2[mt][nt][0], acc2[mt][nt][1]);
            *(__nv_bfloat162*)&sabase[(size_t)((d0+8)*4 + h)*NNT + nc] =
                __floats2bfloat162_rn(acc2[mt][nt][2], acc2[mt][nt][3]);
        }
    }
}

// ---------------- launch ----------------
extern "C" void kernel_launch(void* const* d_in, const int* in_sizes, int n_in,
                              void* d_out, int out_size)
{
    const float* x      = (const float*)d_in[0];
    const float* pos    = (const float*)d_in[1];
    const float* ln_g   = (const float*)d_in[2];
    const float* ln_b   = (const float*)d_in[3];
    const float* gamma  = (const float*)d_in[4];
    const float* temp2  = (const float*)d_in[5];
    const float* w_qkv  = (const float*)d_in[6];
    const float* w_e    = (const float*)d_in[7];
    const float* b_e    = (const float*)d_in[8];
    const float* w_pool = (const float*)d_in[9];
    const float* b_pool = (const float*)d_in[10];
    const float* w_fc1  = (const float*)d_in[11];
    const float* w_fc2  = (const float*)d_in[12];
    const float* b_out1 = (const float*)d_in[14];
    const float* b_out2 = (const float*)d_in[16];
    const float* w_c1   = (const float*)d_in[17];
    const float* b_c1   = (const float*)d_in[18];
    const float* w_c2   = (const float*)d_in[19];
    const float* b_c2   = (const float*)d_in[20];

    __nv_bfloat16 *p_h1b, *p_c2b, *p_xtbf, *p_xctbf, *p_sabf;
    __nv_bfloat16 *p_wq, *p_w1, *p_w2, *p_qkvbf;
    float *p_gate, *p_zero;
    cudaGetSymbolAddress((void**)&p_h1b,   g_h1b);
    cudaGetSymbolAddress((void**)&p_c2b,   g_c2b);
    cudaGetSymbolAddress((void**)&p_xtbf,  g_xt_bf);
    cudaGetSymbolAddress((void**)&p_xctbf, g_xct_bf);
    cudaGetSymbolAddress((void**)&p_qkvbf, g_qkv_bf);
    cudaGetSymbolAddress((void**)&p_sabf,  g_sa_bf);
    cudaGetSymbolAddress((void**)&p_wq,    g_wqkv_bf);
    cudaGetSymbolAddress((void**)&p_w1,    g_wo1_bf);
    cudaGetSymbolAddress((void**)&p_w2,    g_wo2_bf);
    cudaGetSymbolAddress((void**)&p_gate,  g_gate);
    cudaGetSymbolAddress((void**)&p_zero,  g_zero);

    static int s_attr_done = 0;
    if (!s_attr_done) {
        cudaFuncSetAttribute(k_megaln,
            cudaFuncAttributeMaxDynamicSharedMemorySize, 55296);
        cudaFuncSetAttribute(k_mma,
            cudaFuncAttributeMaxDynamicSharedMemorySize, 71680);
        s_attr_done = 1;
    }

    k_init <<<3456, 256>>>(w_qkv, (const float*)d_in[13],
                           (const float*)d_in[15], w_e);
    // MHCResBlock: grouped convs via HMMA with fused stats
    k_convmma<<<dim3(27,16), 256>>>(x, (const __nv_bfloat16*)0, w_c1, b_c1, p_h1b,
                                    (const float*)0, (const float*)0,
                                    p_zero + ZOFF_CS1S, p_zero + ZOFF_CS1Q);
    k_convmma<<<dim3(27,16), 256>>>((const float*)0, p_h1b, w_c2, b_c2, p_c2b,
                                    p_zero + ZOFF_CS1S, p_zero + ZOFF_CS1Q,
                                    p_zero + ZOFF_CS2S, p_zero + ZOFF_CS2Q);
    // mega-fused transpose + xc + double-LN + pool + d_out(x_n)
    k_megaln<<<dim3(432, BB), 256, 55296>>>(x, pos, ln_g, ln_b, w_pool,
                                            (float*)d_out);
    // qkv (pipelined bf16 HMMA, fused q sum-squares + fused K/V low-rank proj)
    k_mma  <<<dim3(6,216,1), 256, 71680>>>(p_xtbf, (const __nv_bfloat16*)0, p_wq,
                                    (const __nv_bfloat16*)0, (const float*)0,
                                    (const float*)0, (const float*)0,
                                    p_qkvbf, 768, 768, 1,
                                    (float*)0, (const float*)0);
    // spatial attention (+ fused CA gate in block 0)
    k_attn <<<dim3(216, BB*NHH), 256>>>(b_e, temp2, b_pool, w_fc1, w_fc2);
    // both output projections with fused gamma-residual into d_out
    k_mma  <<<dim3(1,216,2), 256, 71680>>>(p_sabf, p_xctbf, p_w1, p_w2,
                                    b_out1, b_out2, p_gate,
                                    (__nv_bfloat16*)0, 128, 256, 0,
                                    (float*)d_out, gamma);
}